// round 1
// baseline (speedup 1.0000x reference)
#include <cuda_runtime.h>
#include <math.h>

#define BATCH 4
#define SEQ 2048
#define DMODEL 256
#define NHEAD 8
#define DHEAD 32
#define NLAYER 4
#define ROWS (BATCH*SEQ)   // 8192

// ---------------- scratch (static device globals; no allocs allowed) ----------------
__device__ float g_h   [ROWS*DMODEL];        // residual stream
__device__ float g_qkv [ROWS*3*DMODEL];      // qkv per layer
__device__ float g_attn[ROWS*DMODEL];        // attention out / ffn2 out
__device__ float g_ffn [ROWS*2*DMODEL];      // proj out / ffn1 out
__device__ float g_cs  [ROWS*32];            // rope cos/sin: [cos_t8, sin_t8, cos_x8, sin_x8]
__device__ float g_Wf  [NLAYER*DMODEL*DMODEL]; // fused out_w @ O_w
__device__ float g_bf  [NLAYER*DMODEL];        // fused out_b @ O_w + O_b

// ---------------- input projection: h[b,n,:] = h_in[b,n,0]*proj_w + proj_b ----------------
__global__ void proj_kernel(const float* __restrict__ hin, const float* __restrict__ pw,
                            const float* __restrict__ pb, float* __restrict__ hout) {
    int row = blockIdx.x, d = threadIdx.x;
    hout[row*DMODEL + d] = hin[row]*pw[d] + pb[d];
}

// ---------------- rope cos/sin tables ----------------
__global__ void freqs_kernel(const float* __restrict__ pos, float* __restrict__ cs) {
    int idx = blockIdx.x*blockDim.x + threadIdx.x;   // ROWS*16
    int row = idx >> 4; int r = idx & 15; int axis = r >> 3; int fi = r & 7;
    float coord = pos[row*2 + axis];
    float inv = powf(10000.f, -(float)fi * 0.125f);
    float ang = coord * 64.f * inv;
    float s, c; sincosf(ang, &s, &c);
    cs[row*32 + axis*16 + fi]     = c;
    cs[row*32 + axis*16 + 8 + fi] = s;
}

// ---------------- fused bias: bf = out_b @ O_w + O_b ----------------
__global__ void fuse_bias_kernel(const float* __restrict__ out_b, const float* __restrict__ O_w,
                                 const float* __restrict__ O_b, float* __restrict__ bf) {
    int l = blockIdx.x, j = threadIdx.x;
    const float* wb = O_w + (size_t)l*DMODEL*DMODEL;
    const float* ob = out_b + l*DMODEL;
    float acc = O_b[l*DMODEL + j];
    for (int i = 0; i < DMODEL; i++) acc = fmaf(ob[i], wb[i*DMODEL + j], acc);
    bf[l*DMODEL + j] = acc;
}

// ---------------- SGEMM: C[M,Nk] = A[M,K] @ W[K,Nk] (+bias)(+relu) ----------------
// BM=BN=64, BK=16, 256 threads, 4x4 micro-tile.
template<int HASB, int RELU>
__global__ void sgemm(const float* __restrict__ A, const float* __restrict__ W,
                      const float* __restrict__ bias, float* __restrict__ C,
                      int M, int K, int Nk) {
    __shared__ float As[16*64];
    __shared__ float Ws[16*64];
    int bm = blockIdx.y*64, bn = blockIdx.x*64;
    int tid = threadIdx.x;
    int tr = (tid >> 4) << 2;     // 0..60
    int tc = (tid & 15) << 2;     // 0..60
    float acc[16];
#pragma unroll
    for (int i = 0; i < 16; i++) acc[i] = 0.f;

    int ar = tid >> 2, ac4 = (tid & 3) << 2;   // A tile: 64 rows x 16 cols
    int wr = tid >> 4, wc4 = (tid & 15) << 2;  // W tile: 16 rows x 64 cols

    for (int k0 = 0; k0 < K; k0 += 16) {
        float4 a = *(const float4*)&A[(size_t)(bm+ar)*K + k0 + ac4];
        As[(ac4+0)*64 + ar] = a.x; As[(ac4+1)*64 + ar] = a.y;
        As[(ac4+2)*64 + ar] = a.z; As[(ac4+3)*64 + ar] = a.w;
        *(float4*)&Ws[wr*64 + wc4] = *(const float4*)&W[(size_t)(k0+wr)*Nk + bn + wc4];
        __syncthreads();
#pragma unroll
        for (int kk = 0; kk < 16; kk++) {
            float4 av = *(const float4*)&As[kk*64 + tr];
            float4 wv = *(const float4*)&Ws[kk*64 + tc];
            acc[ 0]=fmaf(av.x,wv.x,acc[ 0]); acc[ 1]=fmaf(av.x,wv.y,acc[ 1]);
            acc[ 2]=fmaf(av.x,wv.z,acc[ 2]); acc[ 3]=fmaf(av.x,wv.w,acc[ 3]);
            acc[ 4]=fmaf(av.y,wv.x,acc[ 4]); acc[ 5]=fmaf(av.y,wv.y,acc[ 5]);
            acc[ 6]=fmaf(av.y,wv.z,acc[ 6]); acc[ 7]=fmaf(av.y,wv.w,acc[ 7]);
            acc[ 8]=fmaf(av.z,wv.x,acc[ 8]); acc[ 9]=fmaf(av.z,wv.y,acc[ 9]);
            acc[10]=fmaf(av.z,wv.z,acc[10]); acc[11]=fmaf(av.z,wv.w,acc[11]);
            acc[12]=fmaf(av.w,wv.x,acc[12]); acc[13]=fmaf(av.w,wv.y,acc[13]);
            acc[14]=fmaf(av.w,wv.z,acc[14]); acc[15]=fmaf(av.w,wv.w,acc[15]);
        }
        __syncthreads();
    }
    float4 bv = make_float4(0.f,0.f,0.f,0.f);
    if (HASB) bv = *(const float4*)&bias[bn + tc];
#pragma unroll
    for (int i = 0; i < 4; i++) {
        float4 r;
        r.x = acc[i*4+0] + bv.x; r.y = acc[i*4+1] + bv.y;
        r.z = acc[i*4+2] + bv.z; r.w = acc[i*4+3] + bv.w;
        if (RELU) { r.x=fmaxf(r.x,0.f); r.y=fmaxf(r.y,0.f); r.z=fmaxf(r.z,0.f); r.w=fmaxf(r.w,0.f); }
        *(float4*)&C[(size_t)(bm+tr+i)*Nk + bn + tc] = r;
    }
}

// ---------------- rope: rotate q and k in-place in g_qkv ----------------
__global__ void rope_kernel(float* __restrict__ qkv, const float* __restrict__ cs) {
    int idx = blockIdx.x*blockDim.x + threadIdx.x;  // ROWS*256 (128 q-pairs + 128 k-pairs per row)
    int row = idx >> 8; int p = idx & 255;
    int isK = p >> 7; int pp = p & 127;
    int head = pp >> 4; int wi = pp & 15;
    int axis = wi >> 3; int i = wi & 7;
    float* base = qkv + (size_t)row*768 + isK*DMODEL + head*DHEAD + axis*16 + i;
    const float* c = cs + row*32 + axis*16;
    float co = c[i], si = c[8 + i];
    float x0 = base[0], x1 = base[8];
    base[0] = x0*co - x1*si;
    base[8] = x1*co + x0*si;
}

// ---------------- attention: flash-style, warp = 2 query rows, 32-key chunks ----------------
__global__ void __launch_bounds__(512) attn_kernel(const float* __restrict__ qkv,
                                                   float* __restrict__ out) {
    int bh = blockIdx.y; int b = bh >> 3; int h = bh & 7;
    int qbase = blockIdx.x * 32;
    int tid = threadIdx.x, w = tid >> 5, lane = tid & 31;
    __shared__ float k_s[32*36];
    __shared__ float v_s[32*36];
    const float* base = qkv + (size_t)b*SEQ*768;

    int qn0 = qbase + w*2, qn1 = qn0 + 1;
    const float* q0p = base + (size_t)qn0*768 + h*DHEAD;
    const float* q1p = base + (size_t)qn1*768 + h*DHEAD;
    float q0[32], q1[32];
#pragma unroll
    for (int d = 0; d < 32; d++) { q0[d] = q0p[d]; q1[d] = q1p[d]; }

    const float scale = 0.17677669529663687f;  // 1/sqrt(32)
    float m0 = -1e30f, m1 = -1e30f, l0 = 0.f, l1 = 0.f, o0 = 0.f, o1 = 0.f;

    for (int kc = 0; kc < SEQ; kc += 32) {
        __syncthreads();
        // cooperative load: 32 keys + 32 values (128B each), float4 per thread
        {
            int t = tid & 255;
            int j = t >> 3, c4 = (t & 7) << 2;
            int off = (tid < 256) ? DMODEL : 2*DMODEL;      // k at +256, v at +512
            float* dst = (tid < 256) ? k_s : v_s;
            const float* src = base + (size_t)(kc + j)*768 + off + h*DHEAD + c4;
            *(float4*)&dst[j*36 + c4] = *(const float4*)src;
        }
        __syncthreads();
        // scores: lane j owns key j
        float s0 = 0.f, s1 = 0.f;
#pragma unroll
        for (int c = 0; c < 8; c++) {
            float4 kv = *(const float4*)&k_s[lane*36 + c*4];
            s0 = fmaf(q0[c*4+0], kv.x, s0); s0 = fmaf(q0[c*4+1], kv.y, s0);
            s0 = fmaf(q0[c*4+2], kv.z, s0); s0 = fmaf(q0[c*4+3], kv.w, s0);
            s1 = fmaf(q1[c*4+0], kv.x, s1); s1 = fmaf(q1[c*4+1], kv.y, s1);
            s1 = fmaf(q1[c*4+2], kv.z, s1); s1 = fmaf(q1[c*4+3], kv.w, s1);
        }
        s0 *= scale; s1 *= scale;
        // online softmax
        float mc0 = s0, mc1 = s1;
#pragma unroll
        for (int off = 16; off; off >>= 1) {
            mc0 = fmaxf(mc0, __shfl_xor_sync(0xffffffffu, mc0, off));
            mc1 = fmaxf(mc1, __shfl_xor_sync(0xffffffffu, mc1, off));
        }
        float mn0 = fmaxf(m0, mc0), mn1 = fmaxf(m1, mc1);
        float c0 = __expf(m0 - mn0), c1 = __expf(m1 - mn1);
        float p0 = __expf(s0 - mn0), p1 = __expf(s1 - mn1);
        float ps0 = p0, ps1 = p1;
#pragma unroll
        for (int off = 16; off; off >>= 1) {
            ps0 += __shfl_xor_sync(0xffffffffu, ps0, off);
            ps1 += __shfl_xor_sync(0xffffffffu, ps1, off);
        }
        l0 = l0*c0 + ps0; l1 = l1*c1 + ps1;
        m0 = mn0; m1 = mn1;
        o0 *= c0; o1 *= c1;
        // accumulate: lane d owns output dim d
#pragma unroll
        for (int j = 0; j < 32; j++) {
            float pj0 = __shfl_sync(0xffffffffu, p0, j);
            float pj1 = __shfl_sync(0xffffffffu, p1, j);
            float vv = v_s[j*36 + lane];
            o0 = fmaf(pj0, vv, o0);
            o1 = fmaf(pj1, vv, o1);
        }
    }
    out[((size_t)(b*SEQ + qn0))*DMODEL + h*DHEAD + lane] = o0 / l0;
    out[((size_t)(b*SEQ + qn1))*DMODEL + h*DHEAD + lane] = o1 / l1;
}

// ---------------- residual add + layernorm (in-place on h) ----------------
__global__ void add_ln_kernel(float* __restrict__ h, const float* __restrict__ o,
                              const float* __restrict__ g, const float* __restrict__ bb) {
    int row = blockIdx.x, t = threadIdx.x;
    int lane = t & 31, wid = t >> 5;
    __shared__ float red[16];
    float x = h[row*DMODEL + t] + o[row*DMODEL + t];
    float s1 = x, s2 = x*x;
#pragma unroll
    for (int off = 16; off; off >>= 1) {
        s1 += __shfl_xor_sync(0xffffffffu, s1, off);
        s2 += __shfl_xor_sync(0xffffffffu, s2, off);
    }
    if (lane == 0) { red[wid] = s1; red[8 + wid] = s2; }
    __syncthreads();
    float t1 = 0.f, t2 = 0.f;
#pragma unroll
    for (int i = 0; i < 8; i++) { t1 += red[i]; t2 += red[8 + i]; }
    float m = t1 * (1.f/DMODEL);
    float var = t2 * (1.f/DMODEL) - m*m;
    float rs = rsqrtf(var + 1e-5f);
    h[row*DMODEL + t] = (x - m)*rs*g[t] + bb[t];
}

// ---------------- host ----------------
extern "C" void kernel_launch(void* const* d_in, const int* in_sizes, int n_in,
                              void* d_out, int out_size) {
    const float* h_in    = (const float*)d_in[0];
    const float* pos     = (const float*)d_in[1];
    const float* proj_w  = (const float*)d_in[2];
    const float* proj_b  = (const float*)d_in[3];
    const float* qkv_w   = (const float*)d_in[4];
    const float* out_w   = (const float*)d_in[5];
    const float* out_b   = (const float*)d_in[6];
    const float* O_w     = (const float*)d_in[7];
    const float* O_b     = (const float*)d_in[8];
    const float* ffn1_w  = (const float*)d_in[9];
    const float* ffn1_b  = (const float*)d_in[10];
    const float* ffn2_w  = (const float*)d_in[11];
    const float* ffn2_b  = (const float*)d_in[12];
    const float* ln1_g   = (const float*)d_in[13];
    const float* ln1_b   = (const float*)d_in[14];
    const float* ln2_g   = (const float*)d_in[15];
    const float* ln2_b   = (const float*)d_in[16];
    const float* final_w = (const float*)d_in[17];
    float* out = (float*)d_out;

    float *ph, *pqkv, *pattn, *pffn, *pcs, *pWf, *pbf;
    cudaGetSymbolAddress((void**)&ph,   g_h);
    cudaGetSymbolAddress((void**)&pqkv, g_qkv);
    cudaGetSymbolAddress((void**)&pattn,g_attn);
    cudaGetSymbolAddress((void**)&pffn, g_ffn);
    cudaGetSymbolAddress((void**)&pcs,  g_cs);
    cudaGetSymbolAddress((void**)&pWf,  g_Wf);
    cudaGetSymbolAddress((void**)&pbf,  g_bf);

    proj_kernel<<<ROWS, 256>>>(h_in, proj_w, proj_b, ph);
    freqs_kernel<<<ROWS*16/256, 256>>>(pos, pcs);
    for (int l = 0; l < NLAYER; l++)
        sgemm<0,0><<<dim3(4,4), 256>>>(out_w + (size_t)l*DMODEL*DMODEL,
                                       O_w  + (size_t)l*DMODEL*DMODEL,
                                       nullptr, pWf + (size_t)l*DMODEL*DMODEL,
                                       DMODEL, DMODEL, DMODEL);
    fuse_bias_kernel<<<NLAYER, 256>>>(out_b, O_w, O_b, pbf);

    for (int l = 0; l < NLAYER; l++) {
        sgemm<0,0><<<dim3(12,128), 256>>>(ph, qkv_w + (size_t)l*DMODEL*3*DMODEL,
                                          nullptr, pqkv, ROWS, DMODEL, 3*DMODEL);
        rope_kernel<<<ROWS, 256>>>(pqkv, pcs);
        attn_kernel<<<dim3(SEQ/32, BATCH*NHEAD), 512>>>(pqkv, pattn);
        sgemm<1,0><<<dim3(4,128), 256>>>(pattn, pWf + (size_t)l*DMODEL*DMODEL,
                                         pbf + l*DMODEL, pffn, ROWS, DMODEL, DMODEL);
        add_ln_kernel<<<ROWS, 256>>>(ph, pffn, ln1_g + l*DMODEL, ln1_b + l*DMODEL);
        sgemm<1,1><<<dim3(8,128), 256>>>(ph, ffn1_w + (size_t)l*DMODEL*2*DMODEL,
                                         ffn1_b + l*2*DMODEL, pffn, ROWS, DMODEL, 2*DMODEL);
        sgemm<1,0><<<dim3(4,128), 256>>>(pffn, ffn2_w + (size_t)l*2*DMODEL*DMODEL,
                                         ffn2_b + l*DMODEL, pattn, ROWS, 2*DMODEL, DMODEL);
        add_ln_kernel<<<ROWS, 256>>>(ph, pattn, ln2_g + l*DMODEL, ln2_b + l*DMODEL);
    }
    sgemm<0,0><<<dim3(4,128), 256>>>(ph, final_w, nullptr, out, ROWS, DMODEL, DMODEL);
}

// round 2
// speedup vs baseline: 3.9438x; 3.9438x over previous
#include <cuda_runtime.h>
#include <math.h>

#define BATCH 4
#define SEQ 2048
#define DMODEL 256
#define NHEAD 8
#define DHEAD 32
#define NLAYER 4
#define ROWS (BATCH*SEQ)   // 8192

// ---------------- scratch ----------------
__device__ float g_h   [ROWS*DMODEL];
__device__ float g_qkv [ROWS*3*DMODEL];
__device__ float g_attn[ROWS*DMODEL];
__device__ float g_ffn [ROWS*2*DMODEL];
__device__ float g_cs  [ROWS*32];
__device__ float g_Wf  [NLAYER*DMODEL*DMODEL];
__device__ float g_bf  [NLAYER*DMODEL];

// ---------------- tf32 helpers ----------------
__device__ __forceinline__ unsigned f2tf32(float f) {
    unsigned u;
    asm("cvt.rna.tf32.f32 %0, %1;" : "=r"(u) : "f"(f));
    return u;
}

__device__ __forceinline__ void mma_tf32(float* d, const unsigned* a, const unsigned* b) {
    asm("mma.sync.aligned.m16n8k8.row.col.f32.tf32.tf32.f32 "
        "{%0,%1,%2,%3},{%4,%5,%6,%7},{%8,%9},{%0,%1,%2,%3};"
        : "+f"(d[0]), "+f"(d[1]), "+f"(d[2]), "+f"(d[3])
        : "r"(a[0]), "r"(a[1]), "r"(a[2]), "r"(a[3]), "r"(b[0]), "r"(b[1]));
}

// ---------------- small setup kernels ----------------
__global__ void proj_kernel(const float* __restrict__ hin, const float* __restrict__ pw,
                            const float* __restrict__ pb, float* __restrict__ hout) {
    int row = blockIdx.x, d = threadIdx.x;
    hout[row*DMODEL + d] = hin[row]*pw[d] + pb[d];
}

__global__ void freqs_kernel(const float* __restrict__ pos, float* __restrict__ cs) {
    int idx = blockIdx.x*blockDim.x + threadIdx.x;   // ROWS*16
    int row = idx >> 4; int r = idx & 15; int axis = r >> 3; int fi = r & 7;
    float coord = pos[row*2 + axis];
    float inv = powf(10000.f, -(float)fi * 0.125f);
    float ang = coord * 64.f * inv;
    float s, c; sincosf(ang, &s, &c);
    cs[row*32 + axis*16 + fi]     = c;
    cs[row*32 + axis*16 + 8 + fi] = s;
}

__global__ void fuse_bias_kernel(const float* __restrict__ out_b, const float* __restrict__ O_w,
                                 const float* __restrict__ O_b, float* __restrict__ bf) {
    int l = blockIdx.x, j = threadIdx.x;
    const float* wb = O_w + (size_t)l*DMODEL*DMODEL;
    const float* ob = out_b + l*DMODEL;
    float acc = O_b[l*DMODEL + j];
    for (int i = 0; i < DMODEL; i++) acc = fmaf(ob[i], wb[i*DMODEL + j], acc);
    bf[l*DMODEL + j] = acc;
}

__global__ void rope_kernel(float* __restrict__ qkv, const float* __restrict__ cs) {
    int idx = blockIdx.x*blockDim.x + threadIdx.x;
    int row = idx >> 8; int p = idx & 255;
    int isK = p >> 7; int pp = p & 127;
    int head = pp >> 4; int wi = pp & 15;
    int axis = wi >> 3; int i = wi & 7;
    float* base = qkv + (size_t)row*768 + isK*DMODEL + head*DHEAD + axis*16 + i;
    const float* c = cs + row*32 + axis*16;
    float co = c[i], si = c[8 + i];
    float x0 = base[0], x1 = base[8];
    base[0] = x0*co - x1*si;
    base[8] = x1*co + x0*si;
}

// ---------------- tf32 tensor-core GEMM: C[M,N] = A[M,K] @ W[K,N] ----------------
// BM=128 BN=64 BK=16, 256 threads (8 warps: 4M x 2N), warp tile 32x32 via 2x4 m16n8k8.
template<int HASB, int RELU>
__global__ void __launch_bounds__(256) gemm_tc(const float* __restrict__ A, const float* __restrict__ W,
                                               const float* __restrict__ bias, float* __restrict__ C,
                                               int M, int K, int N) {
    __shared__ unsigned As[128*20];   // [m][k], pad 20 -> conflict-free frag loads
    __shared__ unsigned Bs[16*72];    // [k][n], pad 72 -> conflict-free frag loads
    int bm = blockIdx.y*128, bn = blockIdx.x*64;
    int tid = threadIdx.x, lane = tid & 31, warp = tid >> 5;
    int wm = (warp >> 1)*32, wn = (warp & 1)*32;
    float acc[2][4][4] = {};

    int arow = tid >> 1, acol = (tid & 1)*8;     // A: 128 rows x 16 k, 8 floats/thread
    int brow = tid >> 4, bcol = (tid & 15)*4;    // B: 16 rows x 64 n, 4 floats/thread

    for (int k0 = 0; k0 < K; k0 += 16) {
        float4 a0 = *(const float4*)&A[(size_t)(bm+arow)*K + k0 + acol];
        float4 a1 = *(const float4*)&A[(size_t)(bm+arow)*K + k0 + acol + 4];
        uint4 u0, u1;
        u0.x = f2tf32(a0.x); u0.y = f2tf32(a0.y); u0.z = f2tf32(a0.z); u0.w = f2tf32(a0.w);
        u1.x = f2tf32(a1.x); u1.y = f2tf32(a1.y); u1.z = f2tf32(a1.z); u1.w = f2tf32(a1.w);
        *(uint4*)&As[arow*20 + acol]     = u0;
        *(uint4*)&As[arow*20 + acol + 4] = u1;
        float4 b = *(const float4*)&W[(size_t)(k0+brow)*N + bn + bcol];
        uint4 ub;
        ub.x = f2tf32(b.x); ub.y = f2tf32(b.y); ub.z = f2tf32(b.z); ub.w = f2tf32(b.w);
        *(uint4*)&Bs[brow*72 + bcol] = ub;
        __syncthreads();
#pragma unroll
        for (int ks = 0; ks < 2; ks++) {
            int kk = ks*8;
            unsigned af[2][4], bf[4][2];
#pragma unroll
            for (int mt = 0; mt < 2; mt++) {
                int r = wm + mt*16 + (lane >> 2);
                int kc = kk + (lane & 3);
                af[mt][0] = As[r*20 + kc];
                af[mt][1] = As[(r+8)*20 + kc];
                af[mt][2] = As[r*20 + kc + 4];
                af[mt][3] = As[(r+8)*20 + kc + 4];
            }
#pragma unroll
            for (int nt = 0; nt < 4; nt++) {
                int c = wn + nt*8 + (lane >> 2);
                int kr = kk + (lane & 3);
                bf[nt][0] = Bs[kr*72 + c];
                bf[nt][1] = Bs[(kr+4)*72 + c];
            }
#pragma unroll
            for (int mt = 0; mt < 2; mt++)
#pragma unroll
                for (int nt = 0; nt < 4; nt++)
                    mma_tf32(acc[mt][nt], af[mt], bf[nt]);
        }
        __syncthreads();
    }
#pragma unroll
    for (int mt = 0; mt < 2; mt++) {
        int r0 = bm + wm + mt*16 + (lane >> 2);
#pragma unroll
        for (int nt = 0; nt < 4; nt++) {
            int c0 = bn + wn + nt*8 + 2*(lane & 3);
            float b0 = 0.f, b1 = 0.f;
            if (HASB) { b0 = bias[c0]; b1 = bias[c0+1]; }
            float v0 = acc[mt][nt][0] + b0, v1 = acc[mt][nt][1] + b1;
            float v2 = acc[mt][nt][2] + b0, v3 = acc[mt][nt][3] + b1;
            if (RELU) { v0=fmaxf(v0,0.f); v1=fmaxf(v1,0.f); v2=fmaxf(v2,0.f); v3=fmaxf(v3,0.f); }
            float2 w0; w0.x = v0; w0.y = v1;
            float2 w1; w1.x = v2; w1.y = v3;
            *(float2*)&C[(size_t)r0*N + c0]     = w0;
            *(float2*)&C[(size_t)(r0+8)*N + c0] = w1;
        }
    }
}

// ---------------- flash attention with tf32 mma ----------------
// Block: one (b,h), 64 q rows. 4 warps, each warp owns 16 q rows (m16).
// Loop over 32-key chunks: S = Q@K^T (mma), online softmax in C-frags, O += P@V (mma).
__global__ void __launch_bounds__(128) attn_tc(const float* __restrict__ qkv,
                                               float* __restrict__ out) {
    int bh = blockIdx.y; int b = bh >> 3; int h = bh & 7;
    int qbase = blockIdx.x * 64;
    int tid = threadIdx.x, lane = tid & 31, w = tid >> 5;
    __shared__ unsigned Qs[64*40];
    __shared__ unsigned Ks[32*40];
    __shared__ unsigned Vs[32*40];
    __shared__ unsigned Ps[64*40];
    const float* base = qkv + (size_t)b*SEQ*768;
    const float scale = 0.17677669529663687f;  // 1/sqrt(32), folded into Q

    // load Q tile 64x32 (scaled, tf32)
    {
        int r = tid >> 1, c = (tid & 1)*16;
        const float* src = base + (size_t)(qbase + r)*768 + h*DHEAD + c;
#pragma unroll
        for (int j = 0; j < 4; j++) {
            float4 v = *(const float4*)(src + j*4);
            uint4 u;
            u.x = f2tf32(v.x*scale); u.y = f2tf32(v.y*scale);
            u.z = f2tf32(v.z*scale); u.w = f2tf32(v.w*scale);
            *(uint4*)&Qs[r*40 + c + j*4] = u;
        }
    }
    __syncthreads();

    // preload Q fragments (reused every chunk)
    unsigned qf[4][4];
#pragma unroll
    for (int ks = 0; ks < 4; ks++) {
        int r = w*16 + (lane >> 2), kc = ks*8 + (lane & 3);
        qf[ks][0] = Qs[r*40 + kc];
        qf[ks][1] = Qs[(r+8)*40 + kc];
        qf[ks][2] = Qs[r*40 + kc + 4];
        qf[ks][3] = Qs[(r+8)*40 + kc + 4];
    }

    float accO[4][4] = {};
    float m0 = -1e30f, m1 = -1e30f, l0 = 0.f, l1 = 0.f;

    for (int kc = 0; kc < SEQ; kc += 32) {
        __syncthreads();
        // load K,V chunk 32x32 each
        {
            int sel = tid >> 6;          // 0: K, 1: V
            int t = tid & 63;
            int r = t >> 1, c = (t & 1)*16;
            const float* src = base + (size_t)(kc + r)*768 + (sel ? 2*DMODEL : DMODEL) + h*DHEAD + c;
            unsigned* dst = sel ? Vs : Ks;
#pragma unroll
            for (int j = 0; j < 4; j++) {
                float4 v = *(const float4*)(src + j*4);
                uint4 u;
                u.x = f2tf32(v.x); u.y = f2tf32(v.y); u.z = f2tf32(v.z); u.w = f2tf32(v.w);
                *(uint4*)&dst[r*40 + c + j*4] = u;
            }
        }
        __syncthreads();

        // S = Q @ K^T : m16 x n32(keys) x k32(dh)
        float s[4][4] = {};
#pragma unroll
        for (int ks = 0; ks < 4; ks++) {
            unsigned bf[4][2];
#pragma unroll
            for (int nt = 0; nt < 4; nt++) {
                int key = nt*8 + (lane >> 2), d = ks*8 + (lane & 3);
                bf[nt][0] = Ks[key*40 + d];
                bf[nt][1] = Ks[key*40 + d + 4];
            }
#pragma unroll
            for (int nt = 0; nt < 4; nt++) mma_tf32(s[nt], qf[ks], bf[nt]);
        }

        // online softmax (rows r = lane/4 and r+8, owned per-thread; quad reduce over keys)
        float rm0 = -1e30f, rm1 = -1e30f;
#pragma unroll
        for (int nt = 0; nt < 4; nt++) {
            rm0 = fmaxf(rm0, fmaxf(s[nt][0], s[nt][1]));
            rm1 = fmaxf(rm1, fmaxf(s[nt][2], s[nt][3]));
        }
        rm0 = fmaxf(rm0, __shfl_xor_sync(0xffffffffu, rm0, 1));
        rm0 = fmaxf(rm0, __shfl_xor_sync(0xffffffffu, rm0, 2));
        rm1 = fmaxf(rm1, __shfl_xor_sync(0xffffffffu, rm1, 1));
        rm1 = fmaxf(rm1, __shfl_xor_sync(0xffffffffu, rm1, 2));
        float mn0 = fmaxf(m0, rm0), mn1 = fmaxf(m1, rm1);
        float cf0 = __expf(m0 - mn0), cf1 = __expf(m1 - mn1);
        m0 = mn0; m1 = mn1;
        float rs0 = 0.f, rs1 = 0.f;
#pragma unroll
        for (int nt = 0; nt < 4; nt++) {
            s[nt][0] = __expf(s[nt][0] - mn0);
            s[nt][1] = __expf(s[nt][1] - mn0);
            s[nt][2] = __expf(s[nt][2] - mn1);
            s[nt][3] = __expf(s[nt][3] - mn1);
            rs0 += s[nt][0] + s[nt][1];
            rs1 += s[nt][2] + s[nt][3];
        }
        rs0 += __shfl_xor_sync(0xffffffffu, rs0, 1);
        rs0 += __shfl_xor_sync(0xffffffffu, rs0, 2);
        rs1 += __shfl_xor_sync(0xffffffffu, rs1, 1);
        rs1 += __shfl_xor_sync(0xffffffffu, rs1, 2);
        l0 = l0*cf0 + rs0; l1 = l1*cf1 + rs1;
#pragma unroll
        for (int nt = 0; nt < 4; nt++) {
            accO[nt][0] *= cf0; accO[nt][1] *= cf0;
            accO[nt][2] *= cf1; accO[nt][3] *= cf1;
        }

        // P -> smem (tf32) for A-fragment reload
#pragma unroll
        for (int nt = 0; nt < 4; nt++) {
            int r = w*16 + (lane >> 2), c = nt*8 + 2*(lane & 3);
            uint2 u0; u0.x = f2tf32(s[nt][0]); u0.y = f2tf32(s[nt][1]);
            uint2 u1; u1.x = f2tf32(s[nt][2]); u1.y = f2tf32(s[nt][3]);
            *(uint2*)&Ps[r*40 + c]     = u0;
            *(uint2*)&Ps[(r+8)*40 + c] = u1;
        }
        __syncwarp();

        // O += P @ V : m16 x n32(dh) x k32(keys)
#pragma unroll
        for (int ks = 0; ks < 4; ks++) {
            unsigned pa[4];
            int r = w*16 + (lane >> 2), kk = ks*8 + (lane & 3);
            pa[0] = Ps[r*40 + kk];
            pa[1] = Ps[(r+8)*40 + kk];
            pa[2] = Ps[r*40 + kk + 4];
            pa[3] = Ps[(r+8)*40 + kk + 4];
            unsigned vb[4][2];
#pragma unroll
            for (int nt = 0; nt < 4; nt++) {
                int key = ks*8 + (lane & 3), d = nt*8 + (lane >> 2);
                vb[nt][0] = Vs[key*40 + d];
                vb[nt][1] = Vs[(key+4)*40 + d];
            }
#pragma unroll
            for (int nt = 0; nt < 4; nt++) mma_tf32(accO[nt], pa, vb[nt]);
        }
    }

    // epilogue
    float il0 = 1.f/l0, il1 = 1.f/l1;
    int qr = qbase + w*16 + (lane >> 2);
#pragma unroll
    for (int nt = 0; nt < 4; nt++) {
        int c = h*DHEAD + nt*8 + 2*(lane & 3);
        float2 v0; v0.x = accO[nt][0]*il0; v0.y = accO[nt][1]*il0;
        float2 v1; v1.x = accO[nt][2]*il1; v1.y = accO[nt][3]*il1;
        *(float2*)&out[(size_t)(b*SEQ + qr)*DMODEL + c]     = v0;
        *(float2*)&out[(size_t)(b*SEQ + qr + 8)*DMODEL + c] = v1;
    }
}

// ---------------- residual add + layernorm ----------------
__global__ void add_ln_kernel(float* __restrict__ h, const float* __restrict__ o,
                              const float* __restrict__ g, const float* __restrict__ bb) {
    int row = blockIdx.x, t = threadIdx.x;
    int lane = t & 31, wid = t >> 5;
    __shared__ float red[16];
    float x = h[row*DMODEL + t] + o[row*DMODEL + t];
    float s1 = x, s2 = x*x;
#pragma unroll
    for (int off = 16; off; off >>= 1) {
        s1 += __shfl_xor_sync(0xffffffffu, s1, off);
        s2 += __shfl_xor_sync(0xffffffffu, s2, off);
    }
    if (lane == 0) { red[wid] = s1; red[8 + wid] = s2; }
    __syncthreads();
    float t1 = 0.f, t2 = 0.f;
#pragma unroll
    for (int i = 0; i < 8; i++) { t1 += red[i]; t2 += red[8 + i]; }
    float m = t1 * (1.f/DMODEL);
    float var = t2 * (1.f/DMODEL) - m*m;
    float rs = rsqrtf(var + 1e-5f);
    h[row*DMODEL + t] = (x - m)*rs*g[t] + bb[t];
}

// ---------------- host ----------------
extern "C" void kernel_launch(void* const* d_in, const int* in_sizes, int n_in,
                              void* d_out, int out_size) {
    const float* h_in    = (const float*)d_in[0];
    const float* pos     = (const float*)d_in[1];
    const float* proj_w  = (const float*)d_in[2];
    const float* proj_b  = (const float*)d_in[3];
    const float* qkv_w   = (const float*)d_in[4];
    const float* out_w   = (const float*)d_in[5];
    const float* out_b   = (const float*)d_in[6];
    const float* O_w     = (const float*)d_in[7];
    const float* O_b     = (const float*)d_in[8];
    const float* ffn1_w  = (const float*)d_in[9];
    const float* ffn1_b  = (const float*)d_in[10];
    const float* ffn2_w  = (const float*)d_in[11];
    const float* ffn2_b  = (const float*)d_in[12];
    const float* ln1_g   = (const float*)d_in[13];
    const float* ln1_b   = (const float*)d_in[14];
    const float* ln2_g   = (const float*)d_in[15];
    const float* ln2_b   = (const float*)d_in[16];
    const float* final_w = (const float*)d_in[17];
    float* out = (float*)d_out;

    float *ph, *pqkv, *pattn, *pffn, *pcs, *pWf, *pbf;
    cudaGetSymbolAddress((void**)&ph,   g_h);
    cudaGetSymbolAddress((void**)&pqkv, g_qkv);
    cudaGetSymbolAddress((void**)&pattn,g_attn);
    cudaGetSymbolAddress((void**)&pffn, g_ffn);
    cudaGetSymbolAddress((void**)&pcs,  g_cs);
    cudaGetSymbolAddress((void**)&pWf,  g_Wf);
    cudaGetSymbolAddress((void**)&pbf,  g_bf);

    proj_kernel<<<ROWS, 256>>>(h_in, proj_w, proj_b, ph);
    freqs_kernel<<<ROWS*16/256, 256>>>(pos, pcs);
    for (int l = 0; l < NLAYER; l++)
        gemm_tc<0,0><<<dim3(4,2), 256>>>(out_w + (size_t)l*DMODEL*DMODEL,
                                         O_w  + (size_t)l*DMODEL*DMODEL,
                                         nullptr, pWf + (size_t)l*DMODEL*DMODEL,
                                         DMODEL, DMODEL, DMODEL);
    fuse_bias_kernel<<<NLAYER, 256>>>(out_b, O_w, O_b, pbf);

    for (int l = 0; l < NLAYER; l++) {
        gemm_tc<0,0><<<dim3(12,64), 256>>>(ph, qkv_w + (size_t)l*DMODEL*3*DMODEL,
                                           nullptr, pqkv, ROWS, DMODEL, 3*DMODEL);
        rope_kernel<<<ROWS, 256>>>(pqkv, pcs);
        attn_tc<<<dim3(SEQ/64, BATCH*NHEAD), 128>>>(pqkv, pattn);
        gemm_tc<1,0><<<dim3(4,64), 256>>>(pattn, pWf + (size_t)l*DMODEL*DMODEL,
                                          pbf + l*DMODEL, pffn, ROWS, DMODEL, DMODEL);
        add_ln_kernel<<<ROWS, 256>>>(ph, pffn, ln1_g + l*DMODEL, ln1_b + l*DMODEL);
        gemm_tc<1,1><<<dim3(8,64), 256>>>(ph, ffn1_w + (size_t)l*DMODEL*2*DMODEL,
                                          ffn1_b + l*2*DMODEL, pffn, ROWS, DMODEL, 2*DMODEL);
        gemm_tc<1,0><<<dim3(4,64), 256>>>(pffn, ffn2_w + (size_t)l*2*DMODEL*DMODEL,
                                          ffn2_b + l*DMODEL, pattn, ROWS, 2*DMODEL, DMODEL);
        add_ln_kernel<<<ROWS, 256>>>(ph, pattn, ln2_g + l*DMODEL, ln2_b + l*DMODEL);
    }
    gemm_tc<0,0><<<dim3(4,64), 256>>>(ph, final_w, nullptr, out, ROWS, DMODEL, DMODEL);
}

// round 4
// speedup vs baseline: 4.5927x; 1.1645x over previous
#include <cuda_runtime.h>
#include <math.h>

#define BATCH 4
#define SEQ 2048
#define DMODEL 256
#define NHEAD 8
#define DHEAD 32
#define NLAYER 4
#define ROWS (BATCH*SEQ)   // 8192

// ---------------- scratch ----------------
__device__ float g_h   [ROWS*DMODEL];
__device__ float g_qkv [ROWS*3*DMODEL];
__device__ float g_attn[ROWS*DMODEL];
__device__ float g_ffn [ROWS*2*DMODEL];
__device__ float g_cs  [ROWS*32];
__device__ float g_Wf  [NLAYER*DMODEL*DMODEL];
__device__ float g_bf  [NLAYER*DMODEL];

// ---------------- tf32 helpers ----------------
__device__ __forceinline__ unsigned f2tf32(float f) {
    unsigned u;
    asm("cvt.rna.tf32.f32 %0, %1;" : "=r"(u) : "f"(f));
    return u;
}

__device__ __forceinline__ void mma_tf32(float* d, const unsigned* a, const unsigned* b) {
    asm("mma.sync.aligned.m16n8k8.row.col.f32.tf32.tf32.f32 "
        "{%0,%1,%2,%3},{%4,%5,%6,%7},{%8,%9},{%0,%1,%2,%3};"
        : "+f"(d[0]), "+f"(d[1]), "+f"(d[2]), "+f"(d[3])
        : "r"(a[0]), "r"(a[1]), "r"(a[2]), "r"(a[3]), "r"(b[0]), "r"(b[1]));
}

__device__ __forceinline__ uint4 cvt4(float4 v) {
    uint4 u;
    u.x = f2tf32(v.x); u.y = f2tf32(v.y); u.z = f2tf32(v.z); u.w = f2tf32(v.w);
    return u;
}

// ---------------- small setup kernels ----------------
__global__ void proj_kernel(const float* __restrict__ hin, const float* __restrict__ pw,
                            const float* __restrict__ pb, float* __restrict__ hout) {
    int row = blockIdx.x, d = threadIdx.x;
    hout[row*DMODEL + d] = hin[row]*pw[d] + pb[d];
}

__global__ void freqs_kernel(const float* __restrict__ pos, float* __restrict__ cs) {
    int idx = blockIdx.x*blockDim.x + threadIdx.x;   // ROWS*16
    int row = idx >> 4; int r = idx & 15; int axis = r >> 3; int fi = r & 7;
    float coord = pos[row*2 + axis];
    float inv = powf(10000.f, -(float)fi * 0.125f);
    float ang = coord * 64.f * inv;
    float s, c; sincosf(ang, &s, &c);
    cs[row*32 + axis*16 + fi]     = c;
    cs[row*32 + axis*16 + 8 + fi] = s;
}

__global__ void fuse_bias_kernel(const float* __restrict__ out_b, const float* __restrict__ O_w,
                                 const float* __restrict__ O_b, float* __restrict__ bf) {
    int l = blockIdx.x, j = threadIdx.x;
    const float* wb = O_w + (size_t)l*DMODEL*DMODEL;
    const float* ob = out_b + l*DMODEL;
    float acc = O_b[l*DMODEL + j];
    for (int i = 0; i < DMODEL; i++) acc = fmaf(ob[i], wb[i*DMODEL + j], acc);
    bf[l*DMODEL + j] = acc;
}

__global__ void rope_kernel(float* __restrict__ qkv, const float* __restrict__ cs) {
    int idx = blockIdx.x*blockDim.x + threadIdx.x;
    int row = idx >> 8; int p = idx & 255;
    int isK = p >> 7; int pp = p & 127;
    int head = pp >> 4; int wi = pp & 15;
    int axis = wi >> 3; int i = wi & 7;
    float* base = qkv + (size_t)row*768 + isK*DMODEL + head*DHEAD + axis*16 + i;
    const float* c = cs + row*32 + axis*16;
    float co = c[i], si = c[8 + i];
    float x0 = base[0], x1 = base[8];
    base[0] = x0*co - x1*si;
    base[8] = x1*co + x0*si;
}

// ---------------- tf32 tensor-core GEMM: C[M,N] = A[M,K] @ W[K,N] ----------------
// BM=128 BN=128 BK=16, 256 threads (8 warps: 2M x 4N), warp tile 64x32.
// Double-buffered smem + register prefetch.
template<int HASB, int RELU>
__global__ void __launch_bounds__(256) gemm_tc(const float* __restrict__ A, const float* __restrict__ W,
                                               const float* __restrict__ bias, float* __restrict__ C,
                                               int M, int K, int N) {
    __shared__ unsigned As[2][128*20];   // [m][k] pad 20
    __shared__ unsigned Bs[2][16*136];   // [k][n] pad 136
    int bm = blockIdx.y*128, bn = blockIdx.x*128;
    int tid = threadIdx.x, lane = tid & 31, warp = tid >> 5;
    int wm = (warp >> 2)*64, wn = (warp & 3)*32;
    float acc[4][4][4] = {};

    int arow = tid >> 1, acol = (tid & 1)*8;    // A: 128x16, 8 floats/thread
    int brow = tid >> 4, bcol = (tid & 15)*8;   // B: 16x128, 8 floats/thread

    const float* Aptr = A + (size_t)(bm+arow)*K + acol;
    const float* Wptr = W + (size_t)brow*N + bn + bcol;

    // first tile -> buf 0
    {
        float4 a0 = *(const float4*)(Aptr);
        float4 a1 = *(const float4*)(Aptr + 4);
        *(uint4*)&As[0][arow*20 + acol]     = cvt4(a0);
        *(uint4*)&As[0][arow*20 + acol + 4] = cvt4(a1);
        float4 b0 = *(const float4*)(Wptr);
        float4 b1 = *(const float4*)(Wptr + 4);
        *(uint4*)&Bs[0][brow*136 + bcol]     = cvt4(b0);
        *(uint4*)&Bs[0][brow*136 + bcol + 4] = cvt4(b1);
    }
    __syncthreads();

    int buf = 0;
    for (int k0 = 0; k0 < K; k0 += 16) {
        float4 pa0, pa1, pb0, pb1;
        bool more = (k0 + 16) < K;
        if (more) {
            pa0 = *(const float4*)(Aptr + k0 + 16);
            pa1 = *(const float4*)(Aptr + k0 + 20);
            pb0 = *(const float4*)(Wptr + (size_t)(k0+16)*N);
            pb1 = *(const float4*)(Wptr + (size_t)(k0+16)*N + 4);
        }
#pragma unroll
        for (int ks = 0; ks < 2; ks++) {
            int kk = ks*8;
            unsigned af[4][4], bf[4][2];
#pragma unroll
            for (int mt = 0; mt < 4; mt++) {
                int r = wm + mt*16 + (lane >> 2);
                int kc = kk + (lane & 3);
                af[mt][0] = As[buf][r*20 + kc];
                af[mt][1] = As[buf][(r+8)*20 + kc];
                af[mt][2] = As[buf][r*20 + kc + 4];
                af[mt][3] = As[buf][(r+8)*20 + kc + 4];
            }
#pragma unroll
            for (int nt = 0; nt < 4; nt++) {
                int c = wn + nt*8 + (lane >> 2);
                int kr = kk + (lane & 3);
                bf[nt][0] = Bs[buf][kr*136 + c];
                bf[nt][1] = Bs[buf][(kr+4)*136 + c];
            }
#pragma unroll
            for (int mt = 0; mt < 4; mt++)
#pragma unroll
                for (int nt = 0; nt < 4; nt++)
                    mma_tf32(acc[mt][nt], af[mt], bf[nt]);
        }
        if (more) {
            int nb = buf ^ 1;
            *(uint4*)&As[nb][arow*20 + acol]     = cvt4(pa0);
            *(uint4*)&As[nb][arow*20 + acol + 4] = cvt4(pa1);
            *(uint4*)&Bs[nb][brow*136 + bcol]     = cvt4(pb0);
            *(uint4*)&Bs[nb][brow*136 + bcol + 4] = cvt4(pb1);
        }
        __syncthreads();
        buf ^= 1;
    }

#pragma unroll
    for (int mt = 0; mt < 4; mt++) {
        int r0 = bm + wm + mt*16 + (lane >> 2);
#pragma unroll
        for (int nt = 0; nt < 4; nt++) {
            int c0 = bn + wn + nt*8 + 2*(lane & 3);
            float b0 = 0.f, b1 = 0.f;
            if (HASB) { b0 = bias[c0]; b1 = bias[c0+1]; }
            float v0 = acc[mt][nt][0] + b0, v1 = acc[mt][nt][1] + b1;
            float v2 = acc[mt][nt][2] + b0, v3 = acc[mt][nt][3] + b1;
            if (RELU) { v0=fmaxf(v0,0.f); v1=fmaxf(v1,0.f); v2=fmaxf(v2,0.f); v3=fmaxf(v3,0.f); }
            float2 w0; w0.x = v0; w0.y = v1;
            float2 w1; w1.x = v2; w1.y = v3;
            *(float2*)&C[(size_t)r0*N + c0]     = w0;
            *(float2*)&C[(size_t)(r0+8)*N + c0] = w1;
        }
    }
}

// ---------------- flash attention with tf32 mma ----------------
// Block: one (b,h), 64 q rows, 4 warps (warp = 16 q rows). 64-key chunks.
// Strides: Qs/Ks = 36, Ps = 68 (64 cols + pad, 68 % 32 == 4), Vs = 40.
__global__ void __launch_bounds__(128) attn_tc(const float* __restrict__ qkv,
                                               float* __restrict__ out) {
    int bh = blockIdx.y; int b = bh >> 3; int h = bh & 7;
    int qbase = blockIdx.x * 64;
    int tid = threadIdx.x, lane = tid & 31, w = tid >> 5;
    __shared__ unsigned Qs[64*36];
    __shared__ unsigned Ks[64*36];
    __shared__ unsigned Vs[64*40];
    __shared__ unsigned Ps[64*68];
    const float* base = qkv + (size_t)b*SEQ*768;
    const float scale = 0.17677669529663687f;  // 1/sqrt(32), folded into Q

    // load Q tile 64x32 (scaled, tf32)
    {
        int r = tid >> 1, c = (tid & 1)*16;
        const float* src = base + (size_t)(qbase + r)*768 + h*DHEAD + c;
#pragma unroll
        for (int j = 0; j < 4; j++) {
            float4 v = *(const float4*)(src + j*4);
            uint4 u;
            u.x = f2tf32(v.x*scale); u.y = f2tf32(v.y*scale);
            u.z = f2tf32(v.z*scale); u.w = f2tf32(v.w*scale);
            *(uint4*)&Qs[r*36 + c + j*4] = u;
        }
    }
    __syncthreads();

    // preload Q fragments
    unsigned qf[4][4];
#pragma unroll
    for (int ks = 0; ks < 4; ks++) {
        int r = w*16 + (lane >> 2), kc = ks*8 + (lane & 3);
        qf[ks][0] = Qs[r*36 + kc];
        qf[ks][1] = Qs[(r+8)*36 + kc];
        qf[ks][2] = Qs[r*36 + kc + 4];
        qf[ks][3] = Qs[(r+8)*36 + kc + 4];
    }

    float accO[4][4] = {};
    float m0 = -1e30f, m1 = -1e30f, l0 = 0.f, l1 = 0.f;

    for (int kc0 = 0; kc0 < SEQ; kc0 += 64) {
        __syncthreads();
        // load K,V chunk 64x32 each
        {
            int r = tid >> 1, c = (tid & 1)*16;
            const float* srcK = base + (size_t)(kc0 + r)*768 + DMODEL + h*DHEAD + c;
#pragma unroll
            for (int j = 0; j < 4; j++) {
                *(uint4*)&Ks[r*36 + c + j*4] = cvt4(*(const float4*)(srcK + j*4));
                *(uint4*)&Vs[r*40 + c + j*4] = cvt4(*(const float4*)(srcK + DMODEL + j*4));
            }
        }
        __syncthreads();

        // S = Q @ K^T : m16 x n64 x k32
        float s[8][4] = {};
#pragma unroll
        for (int ks = 0; ks < 4; ks++) {
#pragma unroll
            for (int nt = 0; nt < 8; nt++) {
                unsigned bfr[2];
                int key = nt*8 + (lane >> 2), d = ks*8 + (lane & 3);
                bfr[0] = Ks[key*36 + d];
                bfr[1] = Ks[key*36 + d + 4];
                mma_tf32(s[nt], qf[ks], bfr);
            }
        }

        // online softmax
        float rm0 = -1e30f, rm1 = -1e30f;
#pragma unroll
        for (int nt = 0; nt < 8; nt++) {
            rm0 = fmaxf(rm0, fmaxf(s[nt][0], s[nt][1]));
            rm1 = fmaxf(rm1, fmaxf(s[nt][2], s[nt][3]));
        }
        rm0 = fmaxf(rm0, __shfl_xor_sync(0xffffffffu, rm0, 1));
        rm0 = fmaxf(rm0, __shfl_xor_sync(0xffffffffu, rm0, 2));
        rm1 = fmaxf(rm1, __shfl_xor_sync(0xffffffffu, rm1, 1));
        rm1 = fmaxf(rm1, __shfl_xor_sync(0xffffffffu, rm1, 2));
        float mn0 = fmaxf(m0, rm0), mn1 = fmaxf(m1, rm1);
        float cf0 = __expf(m0 - mn0), cf1 = __expf(m1 - mn1);
        m0 = mn0; m1 = mn1;
        float rs0 = 0.f, rs1 = 0.f;
#pragma unroll
        for (int nt = 0; nt < 8; nt++) {
            s[nt][0] = __expf(s[nt][0] - mn0);
            s[nt][1] = __expf(s[nt][1] - mn0);
            s[nt][2] = __expf(s[nt][2] - mn1);
            s[nt][3] = __expf(s[nt][3] - mn1);
            rs0 += s[nt][0] + s[nt][1];
            rs1 += s[nt][2] + s[nt][3];
        }
        rs0 += __shfl_xor_sync(0xffffffffu, rs0, 1);
        rs0 += __shfl_xor_sync(0xffffffffu, rs0, 2);
        rs1 += __shfl_xor_sync(0xffffffffu, rs1, 1);
        rs1 += __shfl_xor_sync(0xffffffffu, rs1, 2);
        l0 = l0*cf0 + rs0; l1 = l1*cf1 + rs1;
#pragma unroll
        for (int nt = 0; nt < 4; nt++) {
            accO[nt][0] *= cf0; accO[nt][1] *= cf0;
            accO[nt][2] *= cf1; accO[nt][3] *= cf1;
        }

        // P -> smem (tf32), warp-private rows
        {
            int r = w*16 + (lane >> 2);
#pragma unroll
            for (int nt = 0; nt < 8; nt++) {
                int c = nt*8 + 2*(lane & 3);
                uint2 u0; u0.x = f2tf32(s[nt][0]); u0.y = f2tf32(s[nt][1]);
                uint2 u1; u1.x = f2tf32(s[nt][2]); u1.y = f2tf32(s[nt][3]);
                *(uint2*)&Ps[r*68 + c]     = u0;
                *(uint2*)&Ps[(r+8)*68 + c] = u1;
            }
        }
        __syncwarp();

        // O += P @ V : m16 x n32 x k64
#pragma unroll
        for (int ks = 0; ks < 8; ks++) {
            int kk = ks*8;
            unsigned pa[4];
            int r = w*16 + (lane >> 2), kcc = kk + (lane & 3);
            pa[0] = Ps[r*68 + kcc];
            pa[1] = Ps[(r+8)*68 + kcc];
            pa[2] = Ps[r*68 + kcc + 4];
            pa[3] = Ps[(r+8)*68 + kcc + 4];
#pragma unroll
            for (int nt = 0; nt < 4; nt++) {
                unsigned vb[2];
                int key = kk + (lane & 3), d = nt*8 + (lane >> 2);
                vb[0] = Vs[key*40 + d];
                vb[1] = Vs[(key+4)*40 + d];
                mma_tf32(accO[nt], pa, vb);
            }
        }
    }

    // epilogue
    float il0 = 1.f/l0, il1 = 1.f/l1;
    int qr = qbase + w*16 + (lane >> 2);
#pragma unroll
    for (int nt = 0; nt < 4; nt++) {
        int c = h*DHEAD + nt*8 + 2*(lane & 3);
        float2 v0; v0.x = accO[nt][0]*il0; v0.y = accO[nt][1]*il0;
        float2 v1; v1.x = accO[nt][2]*il1; v1.y = accO[nt][3]*il1;
        *(float2*)&out[(size_t)(b*SEQ + qr)*DMODEL + c]     = v0;
        *(float2*)&out[(size_t)(b*SEQ + qr + 8)*DMODEL + c] = v1;
    }
}

// ---------------- residual add + layernorm ----------------
__global__ void add_ln_kernel(float* __restrict__ h, const float* __restrict__ o,
                              const float* __restrict__ g, const float* __restrict__ bb) {
    int row = blockIdx.x, t = threadIdx.x;
    int lane = t & 31, wid = t >> 5;
    __shared__ float red[16];
    float x = h[row*DMODEL + t] + o[row*DMODEL + t];
    float s1 = x, s2 = x*x;
#pragma unroll
    for (int off = 16; off; off >>= 1) {
        s1 += __shfl_xor_sync(0xffffffffu, s1, off);
        s2 += __shfl_xor_sync(0xffffffffu, s2, off);
    }
    if (lane == 0) { red[wid] = s1; red[8 + wid] = s2; }
    __syncthreads();
    float t1 = 0.f, t2 = 0.f;
#pragma unroll
    for (int i = 0; i < 8; i++) { t1 += red[i]; t2 += red[8 + i]; }
    float m = t1 * (1.f/DMODEL);
    float var = t2 * (1.f/DMODEL) - m*m;
    float rs = rsqrtf(var + 1e-5f);
    h[row*DMODEL + t] = (x - m)*rs*g[t] + bb[t];
}

// ---------------- host ----------------
extern "C" void kernel_launch(void* const* d_in, const int* in_sizes, int n_in,
                              void* d_out, int out_size) {
    const float* h_in    = (const float*)d_in[0];
    const float* pos     = (const float*)d_in[1];
    const float* proj_w  = (const float*)d_in[2];
    const float* proj_b  = (const float*)d_in[3];
    const float* qkv_w   = (const float*)d_in[4];
    const float* out_w   = (const float*)d_in[5];
    const float* out_b   = (const float*)d_in[6];
    const float* O_w     = (const float*)d_in[7];
    const float* O_b     = (const float*)d_in[8];
    const float* ffn1_w  = (const float*)d_in[9];
    const float* ffn1_b  = (const float*)d_in[10];
    const float* ffn2_w  = (const float*)d_in[11];
    const float* ffn2_b  = (const float*)d_in[12];
    const float* ln1_g   = (const float*)d_in[13];
    const float* ln1_b   = (const float*)d_in[14];
    const float* ln2_g   = (const float*)d_in[15];
    const float* ln2_b   = (const float*)d_in[16];
    const float* final_w = (const float*)d_in[17];
    float* out = (float*)d_out;

    float *ph, *pqkv, *pattn, *pffn, *pcs, *pWf, *pbf;
    cudaGetSymbolAddress((void**)&ph,   g_h);
    cudaGetSymbolAddress((void**)&pqkv, g_qkv);
    cudaGetSymbolAddress((void**)&pattn,g_attn);
    cudaGetSymbolAddress((void**)&pffn, g_ffn);
    cudaGetSymbolAddress((void**)&pcs,  g_cs);
    cudaGetSymbolAddress((void**)&pWf,  g_Wf);
    cudaGetSymbolAddress((void**)&pbf,  g_bf);

    proj_kernel<<<ROWS, 256>>>(h_in, proj_w, proj_b, ph);
    freqs_kernel<<<ROWS*16/256, 256>>>(pos, pcs);
    for (int l = 0; l < NLAYER; l++)
        gemm_tc<0,0><<<dim3(2,2), 256>>>(out_w + (size_t)l*DMODEL*DMODEL,
                                         O_w  + (size_t)l*DMODEL*DMODEL,
                                         nullptr, pWf + (size_t)l*DMODEL*DMODEL,
                                         DMODEL, DMODEL, DMODEL);
    fuse_bias_kernel<<<NLAYER, 256>>>(out_b, O_w, O_b, pbf);

    for (int l = 0; l < NLAYER; l++) {
        gemm_tc<0,0><<<dim3(6,64), 256>>>(ph, qkv_w + (size_t)l*DMODEL*3*DMODEL,
                                          nullptr, pqkv, ROWS, DMODEL, 3*DMODEL);
        rope_kernel<<<ROWS, 256>>>(pqkv, pcs);
        attn_tc<<<dim3(SEQ/64, BATCH*NHEAD), 128>>>(pqkv, pattn);
        gemm_tc<1,0><<<dim3(2,64), 256>>>(pattn, pWf + (size_t)l*DMODEL*DMODEL,
                                          pbf + l*DMODEL, pffn, ROWS, DMODEL, DMODEL);
        add_ln_kernel<<<ROWS, 256>>>(ph, pffn, ln1_g + l*DMODEL, ln1_b + l*DMODEL);
        gemm_tc<1,1><<<dim3(4,64), 256>>>(ph, ffn1_w + (size_t)l*DMODEL*2*DMODEL,
                                          ffn1_b + l*2*DMODEL, pffn, ROWS, DMODEL, 2*DMODEL);
        gemm_tc<1,0><<<dim3(2,64), 256>>>(pffn, ffn2_w + (size_t)l*2*DMODEL*DMODEL,
                                          ffn2_b + l*DMODEL, pattn, ROWS, 2*DMODEL, DMODEL);
        add_ln_kernel<<<ROWS, 256>>>(ph, pattn, ln2_g + l*DMODEL, ln2_b + l*DMODEL);
    }
    gemm_tc<0,0><<<dim3(2,64), 256>>>(ph, final_w, nullptr, out, ROWS, DMODEL, DMODEL);
}

// round 5
// speedup vs baseline: 4.8027x; 1.0457x over previous
#include <cuda_runtime.h>
#include <math.h>

#define BATCH 4
#define SEQ 2048
#define DMODEL 256
#define NHEAD 8
#define DHEAD 32
#define NLAYER 4
#define ROWS (BATCH*SEQ)   // 8192

// ---------------- scratch ----------------
__device__ float g_h   [ROWS*DMODEL];
__device__ float g_qkv [ROWS*3*DMODEL];
__device__ float g_attn[ROWS*DMODEL];
__device__ float g_ffn [ROWS*2*DMODEL];
__device__ float g_cs  [ROWS*32];
__device__ float g_Wf  [NLAYER*DMODEL*DMODEL];
__device__ float g_bf  [NLAYER*DMODEL];

// attention smem: Qs 128*36 + Ks 64*36 + Vs 64*40 + Ps 128*68 (words)
#define ATTN_SMEM_WORDS (128*36 + 64*36 + 64*40 + 128*68)
#define ATTN_SMEM_BYTES (ATTN_SMEM_WORDS*4)

// ---------------- tf32 helpers ----------------
__device__ __forceinline__ unsigned f2tf32(float f) {
    unsigned u;
    asm("cvt.rna.tf32.f32 %0, %1;" : "=r"(u) : "f"(f));
    return u;
}

__device__ __forceinline__ void mma_tf32(float* d, const unsigned* a, const unsigned* b) {
    asm("mma.sync.aligned.m16n8k8.row.col.f32.tf32.tf32.f32 "
        "{%0,%1,%2,%3},{%4,%5,%6,%7},{%8,%9},{%0,%1,%2,%3};"
        : "+f"(d[0]), "+f"(d[1]), "+f"(d[2]), "+f"(d[3])
        : "r"(a[0]), "r"(a[1]), "r"(a[2]), "r"(a[3]), "r"(b[0]), "r"(b[1]));
}

__device__ __forceinline__ uint4 cvt4(float4 v) {
    uint4 u;
    u.x = f2tf32(v.x); u.y = f2tf32(v.y); u.z = f2tf32(v.z); u.w = f2tf32(v.w);
    return u;
}

// ---------------- small setup kernels ----------------
__global__ void proj_kernel(const float* __restrict__ hin, const float* __restrict__ pw,
                            const float* __restrict__ pb, float* __restrict__ hout) {
    int row = blockIdx.x, d = threadIdx.x;
    hout[row*DMODEL + d] = hin[row]*pw[d] + pb[d];
}

__global__ void freqs_kernel(const float* __restrict__ pos, float* __restrict__ cs) {
    int idx = blockIdx.x*blockDim.x + threadIdx.x;   // ROWS*16
    int row = idx >> 4; int r = idx & 15; int axis = r >> 3; int fi = r & 7;
    float coord = pos[row*2 + axis];
    float inv = powf(10000.f, -(float)fi * 0.125f);
    float ang = coord * 64.f * inv;
    float s, c; sincosf(ang, &s, &c);
    cs[row*32 + axis*16 + fi]     = c;
    cs[row*32 + axis*16 + 8 + fi] = s;
}

__global__ void fuse_bias_kernel(const float* __restrict__ out_b, const float* __restrict__ O_w,
                                 const float* __restrict__ O_b, float* __restrict__ bf) {
    int l = blockIdx.x, j = threadIdx.x;
    const float* wb = O_w + (size_t)l*DMODEL*DMODEL;
    const float* ob = out_b + l*DMODEL;
    float acc = O_b[l*DMODEL + j];
    for (int i = 0; i < DMODEL; i++) acc = fmaf(ob[i], wb[i*DMODEL + j], acc);
    bf[l*DMODEL + j] = acc;
}

__global__ void rope_kernel(float* __restrict__ qkv, const float* __restrict__ cs) {
    int idx = blockIdx.x*blockDim.x + threadIdx.x;
    int row = idx >> 8; int p = idx & 255;
    int isK = p >> 7; int pp = p & 127;
    int head = pp >> 4; int wi = pp & 15;
    int axis = wi >> 3; int i = wi & 7;
    float* base = qkv + (size_t)row*768 + isK*DMODEL + head*DHEAD + axis*16 + i;
    const float* c = cs + row*32 + axis*16;
    float co = c[i], si = c[8 + i];
    float x0 = base[0], x1 = base[8];
    base[0] = x0*co - x1*si;
    base[8] = x1*co + x0*si;
}

// ---------------- tf32 GEMM, BM=128 BN=128 BK=16 (8 warps: 2M x 4N, warp 64x32) ----------------
template<int HASB, int RELU>
__global__ void __launch_bounds__(256) gemm_tc(const float* __restrict__ A, const float* __restrict__ W,
                                               const float* __restrict__ bias, float* __restrict__ C,
                                               int M, int K, int N) {
    __shared__ unsigned As[2][128*20];
    __shared__ unsigned Bs[2][16*136];
    int bm = blockIdx.y*128, bn = blockIdx.x*128;
    int tid = threadIdx.x, lane = tid & 31, warp = tid >> 5;
    int wm = (warp >> 2)*64, wn = (warp & 3)*32;
    float acc[4][4][4] = {};

    int arow = tid >> 1, acol = (tid & 1)*8;
    int brow = tid >> 4, bcol = (tid & 15)*8;

    const float* Aptr = A + (size_t)(bm+arow)*K + acol;
    const float* Wptr = W + (size_t)brow*N + bn + bcol;

    {
        *(uint4*)&As[0][arow*20 + acol]     = cvt4(*(const float4*)(Aptr));
        *(uint4*)&As[0][arow*20 + acol + 4] = cvt4(*(const float4*)(Aptr + 4));
        *(uint4*)&Bs[0][brow*136 + bcol]     = cvt4(*(const float4*)(Wptr));
        *(uint4*)&Bs[0][brow*136 + bcol + 4] = cvt4(*(const float4*)(Wptr + 4));
    }
    __syncthreads();

    int buf = 0;
    for (int k0 = 0; k0 < K; k0 += 16) {
        float4 pa0, pa1, pb0, pb1;
        bool more = (k0 + 16) < K;
        if (more) {
            pa0 = *(const float4*)(Aptr + k0 + 16);
            pa1 = *(const float4*)(Aptr + k0 + 20);
            pb0 = *(const float4*)(Wptr + (size_t)(k0+16)*N);
            pb1 = *(const float4*)(Wptr + (size_t)(k0+16)*N + 4);
        }
#pragma unroll
        for (int ks = 0; ks < 2; ks++) {
            int kk = ks*8;
            unsigned af[4][4], bf[4][2];
#pragma unroll
            for (int mt = 0; mt < 4; mt++) {
                int r = wm + mt*16 + (lane >> 2);
                int kc = kk + (lane & 3);
                af[mt][0] = As[buf][r*20 + kc];
                af[mt][1] = As[buf][(r+8)*20 + kc];
                af[mt][2] = As[buf][r*20 + kc + 4];
                af[mt][3] = As[buf][(r+8)*20 + kc + 4];
            }
#pragma unroll
            for (int nt = 0; nt < 4; nt++) {
                int c = wn + nt*8 + (lane >> 2);
                int kr = kk + (lane & 3);
                bf[nt][0] = Bs[buf][kr*136 + c];
                bf[nt][1] = Bs[buf][(kr+4)*136 + c];
            }
#pragma unroll
            for (int mt = 0; mt < 4; mt++)
#pragma unroll
                for (int nt = 0; nt < 4; nt++)
                    mma_tf32(acc[mt][nt], af[mt], bf[nt]);
        }
        if (more) {
            int nb = buf ^ 1;
            *(uint4*)&As[nb][arow*20 + acol]     = cvt4(pa0);
            *(uint4*)&As[nb][arow*20 + acol + 4] = cvt4(pa1);
            *(uint4*)&Bs[nb][brow*136 + bcol]     = cvt4(pb0);
            *(uint4*)&Bs[nb][brow*136 + bcol + 4] = cvt4(pb1);
        }
        __syncthreads();
        buf ^= 1;
    }

#pragma unroll
    for (int mt = 0; mt < 4; mt++) {
        int r0 = bm + wm + mt*16 + (lane >> 2);
#pragma unroll
        for (int nt = 0; nt < 4; nt++) {
            int c0 = bn + wn + nt*8 + 2*(lane & 3);
            float b0 = 0.f, b1 = 0.f;
            if (HASB) { b0 = bias[c0]; b1 = bias[c0+1]; }
            float v0 = acc[mt][nt][0] + b0, v1 = acc[mt][nt][1] + b1;
            float v2 = acc[mt][nt][2] + b0, v3 = acc[mt][nt][3] + b1;
            if (RELU) { v0=fmaxf(v0,0.f); v1=fmaxf(v1,0.f); v2=fmaxf(v2,0.f); v3=fmaxf(v3,0.f); }
            float2 w0; w0.x = v0; w0.y = v1;
            float2 w1; w1.x = v2; w1.y = v3;
            *(float2*)&C[(size_t)r0*N + c0]     = w0;
            *(float2*)&C[(size_t)(r0+8)*N + c0] = w1;
        }
    }
}

// ---------------- tf32 GEMM, BM=64 BN=128 BK=16 (8 warps: 2M x 4N, warp 32x32) ----------------
// More blocks for N=256 GEMMs -> full-chip grids.
template<int HASB, int RELU>
__global__ void __launch_bounds__(256) gemm64(const float* __restrict__ A, const float* __restrict__ W,
                                              const float* __restrict__ bias, float* __restrict__ C,
                                              int M, int K, int N) {
    __shared__ unsigned As[2][64*20];
    __shared__ unsigned Bs[2][16*136];
    int bm = blockIdx.y*64, bn = blockIdx.x*128;
    int tid = threadIdx.x, lane = tid & 31, warp = tid >> 5;
    int wm = (warp >> 2)*32, wn = (warp & 3)*32;
    float acc[2][4][4] = {};

    int arow = tid >> 2, acol = (tid & 3)*4;    // 64x16, one float4/thread
    int brow = tid >> 4, bcol = (tid & 15)*8;

    const float* Aptr = A + (size_t)(bm+arow)*K + acol;
    const float* Wptr = W + (size_t)brow*N + bn + bcol;

    {
        *(uint4*)&As[0][arow*20 + acol]      = cvt4(*(const float4*)(Aptr));
        *(uint4*)&Bs[0][brow*136 + bcol]     = cvt4(*(const float4*)(Wptr));
        *(uint4*)&Bs[0][brow*136 + bcol + 4] = cvt4(*(const float4*)(Wptr + 4));
    }
    __syncthreads();

    int buf = 0;
    for (int k0 = 0; k0 < K; k0 += 16) {
        float4 pa0, pb0, pb1;
        bool more = (k0 + 16) < K;
        if (more) {
            pa0 = *(const float4*)(Aptr + k0 + 16);
            pb0 = *(const float4*)(Wptr + (size_t)(k0+16)*N);
            pb1 = *(const float4*)(Wptr + (size_t)(k0+16)*N + 4);
        }
#pragma unroll
        for (int ks = 0; ks < 2; ks++) {
            int kk = ks*8;
            unsigned af[2][4], bf[4][2];
#pragma unroll
            for (int mt = 0; mt < 2; mt++) {
                int r = wm + mt*16 + (lane >> 2);
                int kc = kk + (lane & 3);
                af[mt][0] = As[buf][r*20 + kc];
                af[mt][1] = As[buf][(r+8)*20 + kc];
                af[mt][2] = As[buf][r*20 + kc + 4];
                af[mt][3] = As[buf][(r+8)*20 + kc + 4];
            }
#pragma unroll
            for (int nt = 0; nt < 4; nt++) {
                int c = wn + nt*8 + (lane >> 2);
                int kr = kk + (lane & 3);
                bf[nt][0] = Bs[buf][kr*136 + c];
                bf[nt][1] = Bs[buf][(kr+4)*136 + c];
            }
#pragma unroll
            for (int mt = 0; mt < 2; mt++)
#pragma unroll
                for (int nt = 0; nt < 4; nt++)
                    mma_tf32(acc[mt][nt], af[mt], bf[nt]);
        }
        if (more) {
            int nb = buf ^ 1;
            *(uint4*)&As[nb][arow*20 + acol]      = cvt4(pa0);
            *(uint4*)&Bs[nb][brow*136 + bcol]     = cvt4(pb0);
            *(uint4*)&Bs[nb][brow*136 + bcol + 4] = cvt4(pb1);
        }
        __syncthreads();
        buf ^= 1;
    }

#pragma unroll
    for (int mt = 0; mt < 2; mt++) {
        int r0 = bm + wm + mt*16 + (lane >> 2);
#pragma unroll
        for (int nt = 0; nt < 4; nt++) {
            int c0 = bn + wn + nt*8 + 2*(lane & 3);
            float b0 = 0.f, b1 = 0.f;
            if (HASB) { b0 = bias[c0]; b1 = bias[c0+1]; }
            float v0 = acc[mt][nt][0] + b0, v1 = acc[mt][nt][1] + b1;
            float v2 = acc[mt][nt][2] + b0, v3 = acc[mt][nt][3] + b1;
            if (RELU) { v0=fmaxf(v0,0.f); v1=fmaxf(v1,0.f); v2=fmaxf(v2,0.f); v3=fmaxf(v3,0.f); }
            float2 w0; w0.x = v0; w0.y = v1;
            float2 w1; w1.x = v2; w1.y = v3;
            *(float2*)&C[(size_t)r0*N + c0]     = w0;
            *(float2*)&C[(size_t)(r0+8)*N + c0] = w1;
        }
    }
}

// ---------------- flash attention, 128 q-rows/block, 8 warps, 64-key chunks ----------------
// Dynamic smem: Qs[128*36] | Ks[64*36] | Vs[64*40] | Ps[128*68].
// K/V gmem loads register-prefetched one chunk ahead.
__global__ void __launch_bounds__(256) attn_tc(const float* __restrict__ qkv,
                                               float* __restrict__ out) {
    extern __shared__ unsigned smem_u[];
    unsigned* Qs = smem_u;                 // 128*36
    unsigned* Ks = Qs + 128*36;            // 64*36
    unsigned* Vs = Ks + 64*36;             // 64*40
    unsigned* Ps = Vs + 64*40;             // 128*68

    int bh = blockIdx.y; int b = bh >> 3; int h = bh & 7;
    int qbase = blockIdx.x * 128;
    int tid = threadIdx.x, lane = tid & 31, w = tid >> 5;
    const float* base = qkv + (size_t)b*SEQ*768;
    const float scale = 0.17677669529663687f;  // 1/sqrt(32), folded into Q

    // load Q tile 128x32 (scaled, tf32)
    {
        int r = tid >> 1, c = (tid & 1)*16;
        const float* src = base + (size_t)(qbase + r)*768 + h*DHEAD + c;
#pragma unroll
        for (int j = 0; j < 4; j++) {
            float4 v = *(const float4*)(src + j*4);
            uint4 u;
            u.x = f2tf32(v.x*scale); u.y = f2tf32(v.y*scale);
            u.z = f2tf32(v.z*scale); u.w = f2tf32(v.w*scale);
            *(uint4*)&Qs[r*36 + c + j*4] = u;
        }
    }
    __syncthreads();

    // preload Q fragments (warp w owns rows w*16 .. w*16+15)
    unsigned qf[4][4];
#pragma unroll
    for (int ks = 0; ks < 4; ks++) {
        int r = w*16 + (lane >> 2), kc = ks*8 + (lane & 3);
        qf[ks][0] = Qs[r*36 + kc];
        qf[ks][1] = Qs[(r+8)*36 + kc];
        qf[ks][2] = Qs[r*36 + kc + 4];
        qf[ks][3] = Qs[(r+8)*36 + kc + 4];
    }

    float accO[4][4] = {};
    float m0 = -1e30f, m1 = -1e30f, l0 = 0.f, l1 = 0.f;

    // K/V loader mapping: 256 threads, 64 rows x 32 cols, 8 floats/thread each of K and V
    int kr = tid >> 2, kc4 = (tid & 3)*8;
    const float* kvp = base + (size_t)kr*768 + DMODEL + h*DHEAD + kc4;

    float4 rk0 = *(const float4*)(kvp);
    float4 rk1 = *(const float4*)(kvp + 4);
    float4 rv0 = *(const float4*)(kvp + DMODEL);
    float4 rv1 = *(const float4*)(kvp + DMODEL + 4);

    for (int kc0 = 0; kc0 < SEQ; kc0 += 64) {
        // commit prefetched chunk to smem
        *(uint4*)&Ks[kr*36 + kc4]     = cvt4(rk0);
        *(uint4*)&Ks[kr*36 + kc4 + 4] = cvt4(rk1);
        *(uint4*)&Vs[kr*40 + kc4]     = cvt4(rv0);
        *(uint4*)&Vs[kr*40 + kc4 + 4] = cvt4(rv1);
        __syncthreads();

        // prefetch next chunk (overlaps with compute below)
        if (kc0 + 64 < SEQ) {
            const float* nxt = kvp + (size_t)(kc0 + 64)*768;
            rk0 = *(const float4*)(nxt);
            rk1 = *(const float4*)(nxt + 4);
            rv0 = *(const float4*)(nxt + DMODEL);
            rv1 = *(const float4*)(nxt + DMODEL + 4);
        }

        // S = Q @ K^T : m16 x n64 x k32
        float s[8][4] = {};
#pragma unroll
        for (int ks = 0; ks < 4; ks++) {
#pragma unroll
            for (int nt = 0; nt < 8; nt++) {
                unsigned bfr[2];
                int key = nt*8 + (lane >> 2), d = ks*8 + (lane & 3);
                bfr[0] = Ks[key*36 + d];
                bfr[1] = Ks[key*36 + d + 4];
                mma_tf32(s[nt], qf[ks], bfr);
            }
        }

        // online softmax
        float rm0 = -1e30f, rm1 = -1e30f;
#pragma unroll
        for (int nt = 0; nt < 8; nt++) {
            rm0 = fmaxf(rm0, fmaxf(s[nt][0], s[nt][1]));
            rm1 = fmaxf(rm1, fmaxf(s[nt][2], s[nt][3]));
        }
        rm0 = fmaxf(rm0, __shfl_xor_sync(0xffffffffu, rm0, 1));
        rm0 = fmaxf(rm0, __shfl_xor_sync(0xffffffffu, rm0, 2));
        rm1 = fmaxf(rm1, __shfl_xor_sync(0xffffffffu, rm1, 1));
        rm1 = fmaxf(rm1, __shfl_xor_sync(0xffffffffu, rm1, 2));
        float mn0 = fmaxf(m0, rm0), mn1 = fmaxf(m1, rm1);
        float cf0 = __expf(m0 - mn0), cf1 = __expf(m1 - mn1);
        m0 = mn0; m1 = mn1;
        float rs0 = 0.f, rs1 = 0.f;
#pragma unroll
        for (int nt = 0; nt < 8; nt++) {
            s[nt][0] = __expf(s[nt][0] - mn0);
            s[nt][1] = __expf(s[nt][1] - mn0);
            s[nt][2] = __expf(s[nt][2] - mn1);
            s[nt][3] = __expf(s[nt][3] - mn1);
            rs0 += s[nt][0] + s[nt][1];
            rs1 += s[nt][2] + s[nt][3];
        }
        rs0 += __shfl_xor_sync(0xffffffffu, rs0, 1);
        rs0 += __shfl_xor_sync(0xffffffffu, rs0, 2);
        rs1 += __shfl_xor_sync(0xffffffffu, rs1, 1);
        rs1 += __shfl_xor_sync(0xffffffffu, rs1, 2);
        l0 = l0*cf0 + rs0; l1 = l1*cf1 + rs1;
#pragma unroll
        for (int nt = 0; nt < 4; nt++) {
            accO[nt][0] *= cf0; accO[nt][1] *= cf0;
            accO[nt][2] *= cf1; accO[nt][3] *= cf1;
        }

        // P -> smem (tf32), warp-private rows
        {
            int r = w*16 + (lane >> 2);
#pragma unroll
            for (int nt = 0; nt < 8; nt++) {
                int c = nt*8 + 2*(lane & 3);
                uint2 u0; u0.x = f2tf32(s[nt][0]); u0.y = f2tf32(s[nt][1]);
                uint2 u1; u1.x = f2tf32(s[nt][2]); u1.y = f2tf32(s[nt][3]);
                *(uint2*)&Ps[r*68 + c]     = u0;
                *(uint2*)&Ps[(r+8)*68 + c] = u1;
            }
        }
        __syncwarp();

        // O += P @ V : m16 x n32 x k64
#pragma unroll
        for (int ks = 0; ks < 8; ks++) {
            int kk = ks*8;
            unsigned pa[4];
            int r = w*16 + (lane >> 2), kcc = kk + (lane & 3);
            pa[0] = Ps[r*68 + kcc];
            pa[1] = Ps[(r+8)*68 + kcc];
            pa[2] = Ps[r*68 + kcc + 4];
            pa[3] = Ps[(r+8)*68 + kcc + 4];
#pragma unroll
            for (int nt = 0; nt < 4; nt++) {
                unsigned vb[2];
                int key = kk + (lane & 3), d = nt*8 + (lane >> 2);
                vb[0] = Vs[key*40 + d];
                vb[1] = Vs[(key+4)*40 + d];
                mma_tf32(accO[nt], pa, vb);
            }
        }
        __syncthreads();   // Ks/Vs consumed; safe to overwrite next iter
    }

    // epilogue
    float il0 = 1.f/l0, il1 = 1.f/l1;
    int qr = qbase + w*16 + (lane >> 2);
#pragma unroll
    for (int nt = 0; nt < 4; nt++) {
        int c = h*DHEAD + nt*8 + 2*(lane & 3);
        float2 v0; v0.x = accO[nt][0]*il0; v0.y = accO[nt][1]*il0;
        float2 v1; v1.x = accO[nt][2]*il1; v1.y = accO[nt][3]*il1;
        *(float2*)&out[(size_t)(b*SEQ + qr)*DMODEL + c]     = v0;
        *(float2*)&out[(size_t)(b*SEQ + qr + 8)*DMODEL + c] = v1;
    }
}

// ---------------- residual add + layernorm ----------------
__global__ void add_ln_kernel(float* __restrict__ h, const float* __restrict__ o,
                              const float* __restrict__ g, const float* __restrict__ bb) {
    int row = blockIdx.x, t = threadIdx.x;
    int lane = t & 31, wid = t >> 5;
    __shared__ float red[16];
    float x = h[row*DMODEL + t] + o[row*DMODEL + t];
    float s1 = x, s2 = x*x;
#pragma unroll
    for (int off = 16; off; off >>= 1) {
        s1 += __shfl_xor_sync(0xffffffffu, s1, off);
        s2 += __shfl_xor_sync(0xffffffffu, s2, off);
    }
    if (lane == 0) { red[wid] = s1; red[8 + wid] = s2; }
    __syncthreads();
    float t1 = 0.f, t2 = 0.f;
#pragma unroll
    for (int i = 0; i < 8; i++) { t1 += red[i]; t2 += red[8 + i]; }
    float m = t1 * (1.f/DMODEL);
    float var = t2 * (1.f/DMODEL) - m*m;
    float rs = rsqrtf(var + 1e-5f);
    h[row*DMODEL + t] = (x - m)*rs*g[t] + bb[t];
}

// ---------------- host ----------------
extern "C" void kernel_launch(void* const* d_in, const int* in_sizes, int n_in,
                              void* d_out, int out_size) {
    const float* h_in    = (const float*)d_in[0];
    const float* pos     = (const float*)d_in[1];
    const float* proj_w  = (const float*)d_in[2];
    const float* proj_b  = (const float*)d_in[3];
    const float* qkv_w   = (const float*)d_in[4];
    const float* out_w   = (const float*)d_in[5];
    const float* out_b   = (const float*)d_in[6];
    const float* O_w     = (const float*)d_in[7];
    const float* O_b     = (const float*)d_in[8];
    const float* ffn1_w  = (const float*)d_in[9];
    const float* ffn1_b  = (const float*)d_in[10];
    const float* ffn2_w  = (const float*)d_in[11];
    const float* ffn2_b  = (const float*)d_in[12];
    const float* ln1_g   = (const float*)d_in[13];
    const float* ln1_b   = (const float*)d_in[14];
    const float* ln2_g   = (const float*)d_in[15];
    const float* ln2_b   = (const float*)d_in[16];
    const float* final_w = (const float*)d_in[17];
    float* out = (float*)d_out;

    float *ph, *pqkv, *pattn, *pffn, *pcs, *pWf, *pbf;
    cudaGetSymbolAddress((void**)&ph,   g_h);
    cudaGetSymbolAddress((void**)&pqkv, g_qkv);
    cudaGetSymbolAddress((void**)&pattn,g_attn);
    cudaGetSymbolAddress((void**)&pffn, g_ffn);
    cudaGetSymbolAddress((void**)&pcs,  g_cs);
    cudaGetSymbolAddress((void**)&pWf,  g_Wf);
    cudaGetSymbolAddress((void**)&pbf,  g_bf);

    cudaFuncSetAttribute(attn_tc, cudaFuncAttributeMaxDynamicSharedMemorySize, ATTN_SMEM_BYTES);

    proj_kernel<<<ROWS, 256>>>(h_in, proj_w, proj_b, ph);
    freqs_kernel<<<ROWS*16/256, 256>>>(pos, pcs);
    for (int l = 0; l < NLAYER; l++)
        gemm_tc<0,0><<<dim3(2,2), 256>>>(out_w + (size_t)l*DMODEL*DMODEL,
                                         O_w  + (size_t)l*DMODEL*DMODEL,
                                         nullptr, pWf + (size_t)l*DMODEL*DMODEL,
                                         DMODEL, DMODEL, DMODEL);
    fuse_bias_kernel<<<NLAYER, 256>>>(out_b, O_w, O_b, pbf);

    for (int l = 0; l < NLAYER; l++) {
        gemm_tc<0,0><<<dim3(6,64), 256>>>(ph, qkv_w + (size_t)l*DMODEL*3*DMODEL,
                                          nullptr, pqkv, ROWS, DMODEL, 3*DMODEL);
        rope_kernel<<<ROWS, 256>>>(pqkv, pcs);
        attn_tc<<<dim3(SEQ/128, BATCH*NHEAD), 256, ATTN_SMEM_BYTES>>>(pqkv, pattn);
        gemm64<1,0><<<dim3(2,128), 256>>>(pattn, pWf + (size_t)l*DMODEL*DMODEL,
                                          pbf + l*DMODEL, pffn, ROWS, DMODEL, DMODEL);
        add_ln_kernel<<<ROWS, 256>>>(ph, pffn, ln1_g + l*DMODEL, ln1_b + l*DMODEL);
        gemm_tc<1,1><<<dim3(4,64), 256>>>(ph, ffn1_w + (size_t)l*DMODEL*2*DMODEL,
                                          ffn1_b + l*2*DMODEL, pffn, ROWS, DMODEL, 2*DMODEL);
        gemm64<1,0><<<dim3(2,128), 256>>>(pffn, ffn2_w + (size_t)l*2*DMODEL*DMODEL,
                                          ffn2_b + l*DMODEL, pattn, ROWS, 2*DMODEL, DMODEL);
        add_ln_kernel<<<ROWS, 256>>>(ph, pattn, ln2_g + l*DMODEL, ln2_b + l*DMODEL);
    }
    gemm64<0,0><<<dim3(2,128), 256>>>(ph, final_w, nullptr, out, ROWS, DMODEL, DMODEL);
}

// round 6
// speedup vs baseline: 6.5742x; 1.3688x over previous
#include <cuda_runtime.h>
#include <cuda_fp16.h>
#include <math.h>

#define BATCH 4
#define SEQ 2048
#define DMODEL 256
#define NHEAD 8
#define DHEAD 32
#define NLAYER 4
#define ROWS (BATCH*SEQ)   // 8192

// ---------------- scratch ----------------
__device__ float g_h   [ROWS*DMODEL];
__device__ float g_qkv [ROWS*3*DMODEL];
__device__ float g_attn[ROWS*DMODEL];
__device__ float g_ffn [ROWS*2*DMODEL];
__device__ float g_cs  [ROWS*32];
__device__ float g_Wf  [NLAYER*DMODEL*DMODEL];
__device__ float g_bf  [NLAYER*DMODEL];

// ---------------- fp16 helpers ----------------
__device__ __forceinline__ unsigned ph2(float a, float b) {
    __half2 h = __floats2half2_rn(a, b);
    return *reinterpret_cast<unsigned*>(&h);
}

__device__ __forceinline__ void mma_h(float* d, const unsigned* a, unsigned b0, unsigned b1) {
    asm("mma.sync.aligned.m16n8k16.row.col.f32.f16.f16.f32 "
        "{%0,%1,%2,%3},{%4,%5,%6,%7},{%8,%9},{%0,%1,%2,%3};"
        : "+f"(d[0]), "+f"(d[1]), "+f"(d[2]), "+f"(d[3])
        : "r"(a[0]), "r"(a[1]), "r"(a[2]), "r"(a[3]), "r"(b0), "r"(b1));
}

__device__ __forceinline__ void ldsm4t(unsigned* r, const void* p) {
    unsigned a = (unsigned)__cvta_generic_to_shared(p);
    asm volatile("ldmatrix.sync.aligned.m8n8.x4.trans.shared.b16 {%0,%1,%2,%3}, [%4];"
        : "=r"(r[0]), "=r"(r[1]), "=r"(r[2]), "=r"(r[3]) : "r"(a));
}

// ---------------- small setup kernels ----------------
__global__ void proj_kernel(const float* __restrict__ hin, const float* __restrict__ pw,
                            const float* __restrict__ pb, float* __restrict__ hout) {
    int row = blockIdx.x, d = threadIdx.x;
    hout[row*DMODEL + d] = hin[row]*pw[d] + pb[d];
}

__global__ void freqs_kernel(const float* __restrict__ pos, float* __restrict__ cs) {
    int idx = blockIdx.x*blockDim.x + threadIdx.x;   // ROWS*16
    int row = idx >> 4; int r = idx & 15; int axis = r >> 3; int fi = r & 7;
    float coord = pos[row*2 + axis];
    float inv = powf(10000.f, -(float)fi * 0.125f);
    float ang = coord * 64.f * inv;
    float s, c; sincosf(ang, &s, &c);
    cs[row*32 + axis*16 + fi]     = c;
    cs[row*32 + axis*16 + 8 + fi] = s;
}

__global__ void fuse_bias_kernel(const float* __restrict__ out_b, const float* __restrict__ O_w,
                                 const float* __restrict__ O_b, float* __restrict__ bf) {
    int l = blockIdx.x, j = threadIdx.x;
    const float* wb = O_w + (size_t)l*DMODEL*DMODEL;
    const float* ob = out_b + l*DMODEL;
    float acc = O_b[l*DMODEL + j];
    for (int i = 0; i < DMODEL; i++) acc = fmaf(ob[i], wb[i*DMODEL + j], acc);
    bf[l*DMODEL + j] = acc;
}

// ---------------- fp16 GEMM: C[M,N] = A[M,K] @ W[K,N] (+bias)(+relu), batched via z ----------------
// BM = MT*32 (MT=4 -> 128, MT=2 -> 64), BN=128, BK=32. 8 warps (2M x 4N).
// A frag: direct LDS from [m][k] half2 stride 20. B frag: ldmatrix.x4.trans from [k][n] halves stride 136.
template<int MT, int HASB, int RELU>
__global__ void __launch_bounds__(256) gemm_h(const float* __restrict__ A, const float* __restrict__ W,
                                              const float* __restrict__ bias, float* __restrict__ C,
                                              int M, int K, int N, int sA, int sW, int sC) {
    __shared__ unsigned As2[2][MT*32*20];
    __shared__ __half  Bsh[2][32*136];
    A += (size_t)blockIdx.z*sA; W += (size_t)blockIdx.z*sW; C += (size_t)blockIdx.z*sC;
    const int BM = MT*32;
    int bm = blockIdx.y*BM, bn = blockIdx.x*128;
    int tid = threadIdx.x, lane = tid & 31, warp = tid >> 5;
    int q = lane >> 2, t = lane & 3;
    int wm = (warp >> 2)*(16*MT), wn = (warp & 3)*32;
    float acc[MT][4][4];
#pragma unroll
    for (int a = 0; a < MT; a++)
#pragma unroll
        for (int b = 0; b < 4; b++)
#pragma unroll
            for (int c = 0; c < 4; c++) acc[a][b][c] = 0.f;

    int arow, acolf;
    if (MT == 4) { arow = tid >> 1; acolf = (tid & 1)*16; }
    else         { arow = tid >> 2; acolf = (tid & 3)*8; }
    int brow = tid >> 4, bcol = (tid & 15)*8;
    const float* Ap = A + (size_t)(bm + arow)*K + acolf;
    const float* Wp = W + (size_t)brow*N + bn + bcol;

    float4 ra[4], rb[4];
    // prologue: load + store stage 0
    ra[0] = *(const float4*)(Ap);
    ra[1] = *(const float4*)(Ap + 4);
    if (MT == 4) { ra[2] = *(const float4*)(Ap + 8); ra[3] = *(const float4*)(Ap + 12); }
    rb[0] = *(const float4*)(Wp);
    rb[1] = *(const float4*)(Wp + 4);
    rb[2] = *(const float4*)(Wp + (size_t)16*N);
    rb[3] = *(const float4*)(Wp + (size_t)16*N + 4);
    {
        *(uint4*)&As2[0][arow*20 + acolf/2] =
            make_uint4(ph2(ra[0].x,ra[0].y), ph2(ra[0].z,ra[0].w), ph2(ra[1].x,ra[1].y), ph2(ra[1].z,ra[1].w));
        if (MT == 4)
            *(uint4*)&As2[0][arow*20 + acolf/2 + 4] =
                make_uint4(ph2(ra[2].x,ra[2].y), ph2(ra[2].z,ra[2].w), ph2(ra[3].x,ra[3].y), ph2(ra[3].z,ra[3].w));
        *(uint4*)&Bsh[0][brow*136 + bcol] =
            make_uint4(ph2(rb[0].x,rb[0].y), ph2(rb[0].z,rb[0].w), ph2(rb[1].x,rb[1].y), ph2(rb[1].z,rb[1].w));
        *(uint4*)&Bsh[0][(brow+16)*136 + bcol] =
            make_uint4(ph2(rb[2].x,rb[2].y), ph2(rb[2].z,rb[2].w), ph2(rb[3].x,rb[3].y), ph2(rb[3].z,rb[3].w));
    }
    __syncthreads();

    int buf = 0;
    for (int k0 = 0; k0 < K; k0 += 32) {
        bool more = (k0 + 32) < K;
        if (more) {
            ra[0] = *(const float4*)(Ap + k0 + 32);
            ra[1] = *(const float4*)(Ap + k0 + 36);
            if (MT == 4) { ra[2] = *(const float4*)(Ap + k0 + 40); ra[3] = *(const float4*)(Ap + k0 + 44); }
            rb[0] = *(const float4*)(Wp + (size_t)(k0+32)*N);
            rb[1] = *(const float4*)(Wp + (size_t)(k0+32)*N + 4);
            rb[2] = *(const float4*)(Wp + (size_t)(k0+48)*N);
            rb[3] = *(const float4*)(Wp + (size_t)(k0+48)*N + 4);
        }
#pragma unroll
        for (int ks = 0; ks < 2; ks++) {
            unsigned af[MT][4];
#pragma unroll
            for (int mt = 0; mt < MT; mt++) {
                int r = wm + mt*16 + q;
                af[mt][0] = As2[buf][r*20 + ks*8 + t];
                af[mt][1] = As2[buf][(r+8)*20 + ks*8 + t];
                af[mt][2] = As2[buf][r*20 + ks*8 + t + 4];
                af[mt][3] = As2[buf][(r+8)*20 + ks*8 + t + 4];
            }
#pragma unroll
            for (int ntp = 0; ntp < 2; ntp++) {
                unsigned bb[4];
                ldsm4t(bb, &Bsh[buf][(ks*16 + (lane & 15))*136 + wn + ntp*16 + (lane >> 4)*8]);
#pragma unroll
                for (int mt = 0; mt < MT; mt++) {
                    mma_h(acc[mt][2*ntp],   af[mt], bb[0], bb[1]);
                    mma_h(acc[mt][2*ntp+1], af[mt], bb[2], bb[3]);
                }
            }
        }
        if (more) {
            int nb = buf ^ 1;
            *(uint4*)&As2[nb][arow*20 + acolf/2] =
                make_uint4(ph2(ra[0].x,ra[0].y), ph2(ra[0].z,ra[0].w), ph2(ra[1].x,ra[1].y), ph2(ra[1].z,ra[1].w));
            if (MT == 4)
                *(uint4*)&As2[nb][arow*20 + acolf/2 + 4] =
                    make_uint4(ph2(ra[2].x,ra[2].y), ph2(ra[2].z,ra[2].w), ph2(ra[3].x,ra[3].y), ph2(ra[3].z,ra[3].w));
            *(uint4*)&Bsh[nb][brow*136 + bcol] =
                make_uint4(ph2(rb[0].x,rb[0].y), ph2(rb[0].z,rb[0].w), ph2(rb[1].x,rb[1].y), ph2(rb[1].z,rb[1].w));
            *(uint4*)&Bsh[nb][(brow+16)*136 + bcol] =
                make_uint4(ph2(rb[2].x,rb[2].y), ph2(rb[2].z,rb[2].w), ph2(rb[3].x,rb[3].y), ph2(rb[3].z,rb[3].w));
        }
        __syncthreads();
        buf ^= 1;
    }

#pragma unroll
    for (int mt = 0; mt < MT; mt++) {
        int r0 = bm + wm + mt*16 + q;
#pragma unroll
        for (int nt = 0; nt < 4; nt++) {
            int c0 = bn + wn + nt*8 + 2*t;
            float b0 = 0.f, b1 = 0.f;
            if (HASB) { b0 = bias[c0]; b1 = bias[c0+1]; }
            float v0 = acc[mt][nt][0] + b0, v1 = acc[mt][nt][1] + b1;
            float v2 = acc[mt][nt][2] + b0, v3 = acc[mt][nt][3] + b1;
            if (RELU) { v0=fmaxf(v0,0.f); v1=fmaxf(v1,0.f); v2=fmaxf(v2,0.f); v3=fmaxf(v3,0.f); }
            float2 w0; w0.x = v0; w0.y = v1;
            float2 w1; w1.x = v2; w1.y = v3;
            *(float2*)&C[(size_t)r0*N + c0]     = w0;
            *(float2*)&C[(size_t)(r0+8)*N + c0] = w1;
        }
    }
}

// ---------------- fp16 flash attention with fused rope ----------------
// Block = (b,h,128 q rows), 8 warps (warp = 16 q rows), 64-key chunks.
// Q2/K2: [row][d] half2, stride 20. Vh: [key][d] halves, stride 40 (ldmatrix.trans source).
// P2: [row][key] half2, stride 36. Rope applied at Q/K smem fill.
__global__ void __launch_bounds__(256) attn_h(const float* __restrict__ qkv,
                                              const float* __restrict__ cs,
                                              float* __restrict__ out) {
    __shared__ unsigned Q2[128*20];
    __shared__ unsigned K2[64*20];
    __shared__ __half  Vh[64*40];
    __shared__ unsigned P2[128*36];

    int bh = blockIdx.y; int b = bh >> 3; int h = bh & 7;
    int qbase = blockIdx.x * 128;
    int tid = threadIdx.x, lane = tid & 31, w = tid >> 5;
    int q = lane >> 2, t = lane & 3;
    const float* base = qkv + (size_t)b*SEQ*768;
    const float scale = 0.17677669529663687f;  // 1/sqrt(32), folded into Q

    // ---- load Q tile 128x32 with rope + scale ----
    {
        int r = tid >> 1, c = (tid & 1)*16;
        int grow = qbase + r;
        const float* src = base + (size_t)grow*768 + h*DHEAD + c;
        float v[16];
        *(float4*)&v[0]  = *(const float4*)(src);
        *(float4*)&v[4]  = *(const float4*)(src + 4);
        *(float4*)&v[8]  = *(const float4*)(src + 8);
        *(float4*)&v[12] = *(const float4*)(src + 12);
        const float* cr = cs + (size_t)(b*SEQ + grow)*32 + (c >> 4)*16;
        float rv[16];
#pragma unroll
        for (int i = 0; i < 8; i++) {
            float co = cr[i], si = cr[8+i];
            rv[i]   = (v[i]*co - v[i+8]*si)*scale;
            rv[i+8] = (v[i+8]*co + v[i]*si)*scale;
        }
        *(uint4*)&Q2[r*20 + c/2] =
            make_uint4(ph2(rv[0],rv[1]), ph2(rv[2],rv[3]), ph2(rv[4],rv[5]), ph2(rv[6],rv[7]));
        *(uint4*)&Q2[r*20 + c/2 + 4] =
            make_uint4(ph2(rv[8],rv[9]), ph2(rv[10],rv[11]), ph2(rv[12],rv[13]), ph2(rv[14],rv[15]));
    }
    __syncthreads();

    // preload Q fragments
    unsigned qf[2][4];
#pragma unroll
    for (int ks = 0; ks < 2; ks++) {
        int r = w*16 + q;
        qf[ks][0] = Q2[r*20 + ks*8 + t];
        qf[ks][1] = Q2[(r+8)*20 + ks*8 + t];
        qf[ks][2] = Q2[r*20 + ks*8 + t + 4];
        qf[ks][3] = Q2[(r+8)*20 + ks*8 + t + 4];
    }

    float accO[4][4] = {};
    float m0 = -1e30f, m1 = -1e30f, l0 = 0.f, l1 = 0.f;

    // ---- K/V loader: warps 0-3 load K (with rope), warps 4-7 load V ----
    int isV = tid >> 7;
    int t2 = tid & 127;
    int kr = t2 >> 1, c = (t2 & 1)*16;
    const float* kvsrc = base + (size_t)kr*768 + (isV ? 2*DMODEL : DMODEL) + h*DHEAD + c;
    const float* csrc  = cs + (size_t)(b*SEQ + kr)*32 + (c >> 4)*16;

    float pv[16], pc[16];
    *(float4*)&pv[0]  = *(const float4*)(kvsrc);
    *(float4*)&pv[4]  = *(const float4*)(kvsrc + 4);
    *(float4*)&pv[8]  = *(const float4*)(kvsrc + 8);
    *(float4*)&pv[12] = *(const float4*)(kvsrc + 12);
    if (!isV) {
        *(float4*)&pc[0]  = *(const float4*)(csrc);
        *(float4*)&pc[4]  = *(const float4*)(csrc + 4);
        *(float4*)&pc[8]  = *(const float4*)(csrc + 8);
        *(float4*)&pc[12] = *(const float4*)(csrc + 12);
    }

    for (int kc0 = 0; kc0 < SEQ; kc0 += 64) {
        // commit prefetched chunk
        if (!isV) {
            float rv[16];
#pragma unroll
            for (int i = 0; i < 8; i++) {
                float co = pc[i], si = pc[8+i];
                rv[i]   = pv[i]*co - pv[i+8]*si;
                rv[i+8] = pv[i+8]*co + pv[i]*si;
            }
            *(uint4*)&K2[kr*20 + c/2] =
                make_uint4(ph2(rv[0],rv[1]), ph2(rv[2],rv[3]), ph2(rv[4],rv[5]), ph2(rv[6],rv[7]));
            *(uint4*)&K2[kr*20 + c/2 + 4] =
                make_uint4(ph2(rv[8],rv[9]), ph2(rv[10],rv[11]), ph2(rv[12],rv[13]), ph2(rv[14],rv[15]));
        } else {
            *(uint4*)&Vh[kr*40 + c] =
                make_uint4(ph2(pv[0],pv[1]), ph2(pv[2],pv[3]), ph2(pv[4],pv[5]), ph2(pv[6],pv[7]));
            *(uint4*)&Vh[kr*40 + c + 8] =
                make_uint4(ph2(pv[8],pv[9]), ph2(pv[10],pv[11]), ph2(pv[12],pv[13]), ph2(pv[14],pv[15]));
        }
        __syncthreads();

        // prefetch next chunk
        if (kc0 + 64 < SEQ) {
            const float* ns = kvsrc + (size_t)(kc0 + 64)*768;
            *(float4*)&pv[0]  = *(const float4*)(ns);
            *(float4*)&pv[4]  = *(const float4*)(ns + 4);
            *(float4*)&pv[8]  = *(const float4*)(ns + 8);
            *(float4*)&pv[12] = *(const float4*)(ns + 12);
            if (!isV) {
                const float* nc = csrc + (size_t)(kc0 + 64)*32;
                *(float4*)&pc[0]  = *(const float4*)(nc);
                *(float4*)&pc[4]  = *(const float4*)(nc + 4);
                *(float4*)&pc[8]  = *(const float4*)(nc + 8);
                *(float4*)&pc[12] = *(const float4*)(nc + 12);
            }
        }

        // S = Q @ K^T : m16 x n64 x k32 (2 k-steps of 16)
        float s[8][4] = {};
#pragma unroll
        for (int ks = 0; ks < 2; ks++) {
#pragma unroll
            for (int nt = 0; nt < 8; nt++) {
                int key = nt*8 + q;
                unsigned b0 = K2[key*20 + ks*8 + t];
                unsigned b1 = K2[key*20 + ks*8 + t + 4];
                mma_h(s[nt], qf[ks], b0, b1);
            }
        }

        // online softmax
        float rm0 = -1e30f, rm1 = -1e30f;
#pragma unroll
        for (int nt = 0; nt < 8; nt++) {
            rm0 = fmaxf(rm0, fmaxf(s[nt][0], s[nt][1]));
            rm1 = fmaxf(rm1, fmaxf(s[nt][2], s[nt][3]));
        }
        rm0 = fmaxf(rm0, __shfl_xor_sync(0xffffffffu, rm0, 1));
        rm0 = fmaxf(rm0, __shfl_xor_sync(0xffffffffu, rm0, 2));
        rm1 = fmaxf(rm1, __shfl_xor_sync(0xffffffffu, rm1, 1));
        rm1 = fmaxf(rm1, __shfl_xor_sync(0xffffffffu, rm1, 2));
        float mn0 = fmaxf(m0, rm0), mn1 = fmaxf(m1, rm1);
        float cf0 = __expf(m0 - mn0), cf1 = __expf(m1 - mn1);
        m0 = mn0; m1 = mn1;
        float rs0 = 0.f, rs1 = 0.f;
#pragma unroll
        for (int nt = 0; nt < 8; nt++) {
            s[nt][0] = __expf(s[nt][0] - mn0);
            s[nt][1] = __expf(s[nt][1] - mn0);
            s[nt][2] = __expf(s[nt][2] - mn1);
            s[nt][3] = __expf(s[nt][3] - mn1);
            rs0 += s[nt][0] + s[nt][1];
            rs1 += s[nt][2] + s[nt][3];
        }
        rs0 += __shfl_xor_sync(0xffffffffu, rs0, 1);
        rs0 += __shfl_xor_sync(0xffffffffu, rs0, 2);
        rs1 += __shfl_xor_sync(0xffffffffu, rs1, 1);
        rs1 += __shfl_xor_sync(0xffffffffu, rs1, 2);
        l0 = l0*cf0 + rs0; l1 = l1*cf1 + rs1;
#pragma unroll
        for (int nt = 0; nt < 4; nt++) {
            accO[nt][0] *= cf0; accO[nt][1] *= cf0;
            accO[nt][2] *= cf1; accO[nt][3] *= cf1;
        }

        // P -> smem (fp16), warp-private rows
        {
            int r = w*16 + q;
#pragma unroll
            for (int nt = 0; nt < 8; nt++) {
                P2[r*36 + nt*4 + t]     = ph2(s[nt][0], s[nt][1]);
                P2[(r+8)*36 + nt*4 + t] = ph2(s[nt][2], s[nt][3]);
            }
        }
        __syncwarp();

        // O += P @ V : m16 x n32 x k64 (4 k-steps of 16, V^T via ldmatrix.trans)
#pragma unroll
        for (int ks = 0; ks < 4; ks++) {
            unsigned pa[4];
            int r = w*16 + q;
            pa[0] = P2[r*36 + ks*8 + t];
            pa[1] = P2[(r+8)*36 + ks*8 + t];
            pa[2] = P2[r*36 + ks*8 + t + 4];
            pa[3] = P2[(r+8)*36 + ks*8 + t + 4];
#pragma unroll
            for (int ntp = 0; ntp < 2; ntp++) {
                unsigned bb[4];
                ldsm4t(bb, &Vh[(ks*16 + (lane & 15))*40 + ntp*16 + (lane >> 4)*8]);
                mma_h(accO[2*ntp],   pa, bb[0], bb[1]);
                mma_h(accO[2*ntp+1], pa, bb[2], bb[3]);
            }
        }
        __syncthreads();   // K2/Vh consumed; safe to overwrite next iter
    }

    // epilogue
    float il0 = 1.f/l0, il1 = 1.f/l1;
    int qr = qbase + w*16 + q;
#pragma unroll
    for (int nt = 0; nt < 4; nt++) {
        int cc = h*DHEAD + nt*8 + 2*t;
        float2 v0; v0.x = accO[nt][0]*il0; v0.y = accO[nt][1]*il0;
        float2 v1; v1.x = accO[nt][2]*il1; v1.y = accO[nt][3]*il1;
        *(float2*)&out[(size_t)(b*SEQ + qr)*DMODEL + cc]     = v0;
        *(float2*)&out[(size_t)(b*SEQ + qr + 8)*DMODEL + cc] = v1;
    }
}

// ---------------- residual add + layernorm ----------------
__global__ void add_ln_kernel(float* __restrict__ h, const float* __restrict__ o,
                              const float* __restrict__ g, const float* __restrict__ bb) {
    int row = blockIdx.x, t = threadIdx.x;
    int lane = t & 31, wid = t >> 5;
    __shared__ float red[16];
    float x = h[row*DMODEL + t] + o[row*DMODEL + t];
    float s1 = x, s2 = x*x;
#pragma unroll
    for (int off = 16; off; off >>= 1) {
        s1 += __shfl_xor_sync(0xffffffffu, s1, off);
        s2 += __shfl_xor_sync(0xffffffffu, s2, off);
    }
    if (lane == 0) { red[wid] = s1; red[8 + wid] = s2; }
    __syncthreads();
    float t1 = 0.f, t2 = 0.f;
#pragma unroll
    for (int i = 0; i < 8; i++) { t1 += red[i]; t2 += red[8 + i]; }
    float m = t1 * (1.f/DMODEL);
    float var = t2 * (1.f/DMODEL) - m*m;
    float rs = rsqrtf(var + 1e-5f);
    h[row*DMODEL + t] = (x - m)*rs*g[t] + bb[t];
}

// ---------------- host ----------------
extern "C" void kernel_launch(void* const* d_in, const int* in_sizes, int n_in,
                              void* d_out, int out_size) {
    const float* h_in    = (const float*)d_in[0];
    const float* pos     = (const float*)d_in[1];
    const float* proj_w  = (const float*)d_in[2];
    const float* proj_b  = (const float*)d_in[3];
    const float* qkv_w   = (const float*)d_in[4];
    const float* out_w   = (const float*)d_in[5];
    const float* out_b   = (const float*)d_in[6];
    const float* O_w     = (const float*)d_in[7];
    const float* O_b     = (const float*)d_in[8];
    const float* ffn1_w  = (const float*)d_in[9];
    const float* ffn1_b  = (const float*)d_in[10];
    const float* ffn2_w  = (const float*)d_in[11];
    const float* ffn2_b  = (const float*)d_in[12];
    const float* ln1_g   = (const float*)d_in[13];
    const float* ln1_b   = (const float*)d_in[14];
    const float* ln2_g   = (const float*)d_in[15];
    const float* ln2_b   = (const float*)d_in[16];
    const float* final_w = (const float*)d_in[17];
    float* out = (float*)d_out;

    float *ph, *pqkv, *pattn, *pffn, *pcs, *pWf, *pbf;
    cudaGetSymbolAddress((void**)&ph,   g_h);
    cudaGetSymbolAddress((void**)&pqkv, g_qkv);
    cudaGetSymbolAddress((void**)&pattn,g_attn);
    cudaGetSymbolAddress((void**)&pffn, g_ffn);
    cudaGetSymbolAddress((void**)&pcs,  g_cs);
    cudaGetSymbolAddress((void**)&pWf,  g_Wf);
    cudaGetSymbolAddress((void**)&pbf,  g_bf);

    // launch order puts attn_h at launch #6 for ncu -s 5 -c 1
    freqs_kernel<<<ROWS*16/256, 256>>>(pos, pcs);                                   // 1
    gemm_h<2,0,0><<<dim3(2,4,4), 256>>>(out_w, O_w, nullptr, pWf,                   // 2 (batched Wf)
                                        DMODEL, DMODEL, DMODEL,
                                        DMODEL*DMODEL, DMODEL*DMODEL, DMODEL*DMODEL);
    fuse_bias_kernel<<<NLAYER, 256>>>(out_b, O_w, O_b, pbf);                        // 3
    proj_kernel<<<ROWS, 256>>>(h_in, proj_w, proj_b, ph);                           // 4

    for (int l = 0; l < NLAYER; l++) {
        gemm_h<4,0,0><<<dim3(6,64), 256>>>(ph, qkv_w + (size_t)l*DMODEL*3*DMODEL,   // 5
                                           nullptr, pqkv, ROWS, DMODEL, 3*DMODEL, 0, 0, 0);
        attn_h<<<dim3(SEQ/128, BATCH*NHEAD), 256>>>(pqkv, pcs, pattn);              // 6
        gemm_h<2,1,0><<<dim3(2,128), 256>>>(pattn, pWf + (size_t)l*DMODEL*DMODEL,
                                            pbf + l*DMODEL, pffn, ROWS, DMODEL, DMODEL, 0, 0, 0);
        add_ln_kernel<<<ROWS, 256>>>(ph, pffn, ln1_g + l*DMODEL, ln1_b + l*DMODEL);
        gemm_h<4,1,1><<<dim3(4,64), 256>>>(ph, ffn1_w + (size_t)l*DMODEL*2*DMODEL,
                                           ffn1_b + l*2*DMODEL, pffn, ROWS, DMODEL, 2*DMODEL, 0, 0, 0);
        gemm_h<2,1,0><<<dim3(2,128), 256>>>(pffn, ffn2_w + (size_t)l*2*DMODEL*DMODEL,
                                            ffn2_b + l*DMODEL, pattn, ROWS, 2*DMODEL, DMODEL, 0, 0, 0);
        add_ln_kernel<<<ROWS, 256>>>(ph, pattn, ln2_g + l*DMODEL, ln2_b + l*DMODEL);
    }
    gemm_h<2,0,0><<<dim3(2,128), 256>>>(ph, final_w, nullptr, out, ROWS, DMODEL, DMODEL, 0, 0, 0);
}